// round 1
// baseline (speedup 1.0000x reference)
#include <cuda_runtime.h>
#include <cstdint>

// Problem constants
#define BB 8
#define TT 32
#define CC 4880
#define DD 64
#define HH 64
#define AA 256
#define NG 256        // 4*H gate width
#define DIN 128       // 2*D
#define CSPLIT 8
#define NGROUP 153    // ceil(4880/32)

// ---------------- scratch (device globals; no allocation) ----------------
__device__ float g_Spart[CSPLIT][TT][BB][DD];   // partial code sums
__device__ float g_Z[2][TT][NG][BB];            // precomputed input projections (dir, t, gate, b)
__device__ float g_lstm_out[BB * TT * 2 * HH];  // [b][t][128]
__device__ float g_e[BB * TT];                  // attention logits

// ---------------- math helpers ----------------
__device__ __forceinline__ float sigf(float x) {
    return 1.0f / (1.0f + __expf(-x));
}
__device__ __forceinline__ float tanhf_fast(float x) {
    // accurate tanh via exp (handles +-inf saturation correctly)
    return 1.0f - 2.0f / (__expf(2.0f * x) + 1.0f);
}

// =========================================================================
// K1: partial sums S[b,t,d] = sum_c x[b,t,c] * emb[c,d]
// grid (32 t, 8 split), 256 threads (8 warps). Warp covers all 64 d (2/lane),
// 4 consecutive c per group-iteration, 8 batches in registers.
// =========================================================================
__global__ void __launch_bounds__(256) k1_codes(const float* __restrict__ x,
                                                const float* __restrict__ emb) {
    const int t = blockIdx.x, split = blockIdx.y;
    const int w = threadIdx.x >> 5, lane = threadIdx.x & 31;
    const int d0 = lane * 2;

    float acc[BB][2];
#pragma unroll
    for (int b = 0; b < BB; b++) { acc[b][0] = 0.f; acc[b][1] = 0.f; }

    for (int gi = split; gi * 32 < CC; gi += CSPLIT) {
        const int c0 = gi * 32 + w * 4;
        if (c0 < CC) {
            float2 e2[4];
#pragma unroll
            for (int ccx = 0; ccx < 4; ccx++)
                e2[ccx] = *(const float2*)&emb[(c0 + ccx) * DD + d0];
#pragma unroll
            for (int b = 0; b < BB; b++) {
                const float4 xv = *(const float4*)&x[(size_t)(b * TT + t) * CC + c0];
                acc[b][0] += xv.x * e2[0].x + xv.y * e2[1].x + xv.z * e2[2].x + xv.w * e2[3].x;
                acc[b][1] += xv.x * e2[0].y + xv.y * e2[1].y + xv.z * e2[2].y + xv.w * e2[3].y;
            }
        }
    }

    __shared__ float2 wp[8][BB][DD / 2];
#pragma unroll
    for (int b = 0; b < BB; b++)
        wp[w][b][lane] = make_float2(acc[b][0], acc[b][1]);
    __syncthreads();

    // reduce 8 warps -> 512 outputs with 256 threads
    for (int o = threadIdx.x; o < BB * DD; o += 256) {
        const int b = o >> 6, d = o & 63;
        float s = 0.f;
#pragma unroll
        for (int ww = 0; ww < 8; ww++) {
            const float2 v = wp[ww][b][d >> 1];
            s += (d & 1) ? v.y : v.x;
        }
        g_Spart[split][t][b][d] = s;
    }
}

// =========================================================================
// K2: per (t,dir): counts, avg_xt, avg_ht, lstm_in, input projection
// grid (32 t, 2 dir), 512 threads.
// =========================================================================
__global__ void __launch_bounds__(512) k2_prep(const float* __restrict__ x,
                                               const float* __restrict__ Wg,
                                               const float* __restrict__ bg,
                                               const float* __restrict__ Wih_f,
                                               const float* __restrict__ b_f,
                                               const float* __restrict__ Wih_b,
                                               const float* __restrict__ b_b) {
    const int t = blockIdx.x, dir = blockIdx.y;
    const int tid = threadIdx.x;
    __shared__ float rows[BB][DIN];   // [b][0:64]=avg_ht, [64:128]=avg_xt
    __shared__ float red[512];
    __shared__ float cnt_sm[BB], has_sm[BB];

    // ---- counts ----
    const int b = tid >> 6, l64 = tid & 63;
    float csum = 0.f;
    for (int c = l64; c < CC; c += 64) csum += x[(size_t)(b * TT + t) * CC + c];
    red[tid] = csum;
    __syncthreads();
#pragma unroll
    for (int s = 32; s > 0; s >>= 1) {
        if (l64 < s) red[tid] += red[tid + s];
        __syncthreads();
    }
    if (l64 == 0) {
        const float cr = red[tid];
        cnt_sm[b] = fmaxf(cr, 1.f);
        has_sm[b] = (cr > 0.f) ? 1.f : 0.f;
    }
    __syncthreads();

    // ---- avg_xt ----
    {
        const int d = tid & 63, bb2 = tid >> 6;
        float s = 0.f;
#pragma unroll
        for (int sp = 0; sp < CSPLIT; sp++) s += g_Spart[sp][t][bb2][d];
        rows[bb2][DD + d] = s / cnt_sm[bb2];
    }
    __syncthreads();

    // ---- avg_ht = avg_xt @ Wg + bg*has ----
    {
        const int d = tid & 63, bb2 = tid >> 6;
        float s = bg[d] * has_sm[bb2];
#pragma unroll 8
        for (int k = 0; k < DD; k++) s += rows[bb2][DD + k] * Wg[k * DD + d];
        rows[bb2][d] = s;
    }
    __syncthreads();

    // ---- z = lstm_in @ Wih + bias ----
    const float* Wih  = dir ? Wih_b : Wih_f;
    const float* bias = dir ? b_b : b_f;
    const int g = tid & 255, bh = tid >> 8;
    const float bv = bias[g];
    float acc0 = bv, acc1 = bv, acc2 = bv, acc3 = bv;
#pragma unroll 4
    for (int k = 0; k < DIN; k++) {
        const float wv = Wih[k * NG + g];
        acc0 += rows[bh * 4 + 0][k] * wv;
        acc1 += rows[bh * 4 + 1][k] * wv;
        acc2 += rows[bh * 4 + 2][k] * wv;
        acc3 += rows[bh * 4 + 3][k] * wv;
    }
    *(float4*)&g_Z[dir][t][g][bh * 4] = make_float4(acc0, acc1, acc2, acc3);
}

// =========================================================================
// K3: bidirectional LSTM. grid=2 (dir), 512 threads, persistent over T.
// z-phase: thread (g, bhalf) computes z[g][b] for 4 b via packed f32x2 FMA
// over k-pairs; weights (paired) register-resident.
// =========================================================================
__global__ void __launch_bounds__(512, 1) k3_lstm(const float* __restrict__ Whh_f,
                                                  const float* __restrict__ Whh_b) {
    const int dir = blockIdx.x;
    const float* Whh = dir ? Whh_b : Whh_f;
    __shared__ float h_sm[BB][HH];
    __shared__ float z_sm[BB][NG];
    const int tid = threadIdx.x;
    const int g = tid & 255, bh = tid >> 8;

    ((float*)h_sm)[tid] = 0.f;   // 512 == 8*64

    // pack weight pairs (k, k+1) into 64-bit regs
    unsigned long long wpk[32];
#pragma unroll
    for (int i = 0; i < 32; i++) {
        const float w0 = Whh[(2 * i) * NG + g];
        const float w1 = Whh[(2 * i + 1) * NG + g];
        asm("mov.b64 %0, {%1, %2};" : "=l"(wpk[i]) : "f"(w0), "f"(w1));
    }

    // cell state for activation threads (tid < 256): cells (2*bp+cell, j)
    const int j = tid & 63, bp = (tid >> 6) & 3;
    float cst0 = 0.f, cst1 = 0.f;
    __syncthreads();

    for (int s = 0; s < TT; s++) {
        const int t = dir ? (TT - 1 - s) : s;
        const float4 zin = *(const float4*)&g_Z[dir][t][g][bh * 4];
        float zout[4];
#pragma unroll
        for (int b4 = 0; b4 < 4; b4++) {
            const int b = bh * 4 + b4;
            unsigned long long acc = 0ull;   // f32x2 (0,0)
            const ulonglong2* hp = (const ulonglong2*)&h_sm[b][0];
#pragma unroll
            for (int i = 0; i < 16; i++) {
                const ulonglong2 hhv = hp[i];
                asm("fma.rn.f32x2 %0, %1, %2, %0;" : "+l"(acc) : "l"(wpk[2 * i]), "l"(hhv.x));
                asm("fma.rn.f32x2 %0, %1, %2, %0;" : "+l"(acc) : "l"(wpk[2 * i + 1]), "l"(hhv.y));
            }
            float lo, hi;
            asm("mov.b64 {%0, %1}, %2;" : "=f"(lo), "=f"(hi) : "l"(acc));
            const float zi = (b4 == 0) ? zin.x : (b4 == 1) ? zin.y : (b4 == 2) ? zin.z : zin.w;
            zout[b4] = zi + lo + hi;
        }
        z_sm[bh * 4 + 0][g] = zout[0];
        z_sm[bh * 4 + 1][g] = zout[1];
        z_sm[bh * 4 + 2][g] = zout[2];
        z_sm[bh * 4 + 3][g] = zout[3];
        __syncthreads();

        if (tid < 256) {
#pragma unroll
            for (int cell = 0; cell < 2; cell++) {
                const int b = 2 * bp + cell;
                const float ziv = z_sm[b][j];
                const float zfv = z_sm[b][64 + j];
                const float zgv = z_sm[b][128 + j];
                const float zov = z_sm[b][192 + j];
                const float ig = sigf(ziv), fg = sigf(zfv);
                const float gg = tanhf_fast(zgv), og = sigf(zov);
                float cprev = cell ? cst1 : cst0;
                const float cnew = fg * cprev + ig * gg;
                if (cell) cst1 = cnew; else cst0 = cnew;
                const float hnew = og * tanhf_fast(cnew);
                h_sm[b][j] = hnew;
                g_lstm_out[(b * TT + t) * (2 * HH) + dir * HH + j] = hnew;
            }
        }
        __syncthreads();
    }
}

// =========================================================================
// K4: attention logits e[b,t] = tanh(row @ Wa + ba) . ua
// grid 64 (4 rows each), 256 threads.
// =========================================================================
__global__ void __launch_bounds__(256) k4_attn(const float* __restrict__ Wa,
                                               const float* __restrict__ ba,
                                               const float* __restrict__ ua) {
    const int bt0 = blockIdx.x * 4;
    const int tid = threadIdx.x;
    __shared__ float rows[4][DIN];
    __shared__ float red[4][256];

    for (int i = tid; i < 4 * DIN; i += 256) {
        const int r = i >> 7, k = i & 127;
        rows[r][k] = g_lstm_out[(bt0 + r) * DIN + k];
    }
    __syncthreads();

    const float bav = ba[tid];
    float a0 = bav, a1 = bav, a2 = bav, a3 = bav;
#pragma unroll 4
    for (int k = 0; k < DIN; k++) {
        const float w = Wa[k * AA + tid];
        a0 += rows[0][k] * w;
        a1 += rows[1][k] * w;
        a2 += rows[2][k] * w;
        a3 += rows[3][k] * w;
    }
    const float uav = ua[tid];
    red[0][tid] = tanhf_fast(a0) * uav;
    red[1][tid] = tanhf_fast(a1) * uav;
    red[2][tid] = tanhf_fast(a2) * uav;
    red[3][tid] = tanhf_fast(a3) * uav;
    __syncthreads();
#pragma unroll
    for (int s = 128; s > 0; s >>= 1) {
        if (tid < s) {
#pragma unroll
            for (int r = 0; r < 4; r++) red[r][tid] += red[r][tid + s];
        }
        __syncthreads();
    }
    if (tid < 4) g_e[bt0 + tid] = red[tid][0];
}

// =========================================================================
// K5: softmax over t, context, leaky_relu, output head. grid 8 (b), 128 thr.
// =========================================================================
__global__ void __launch_bounds__(128) k5_head(const float* __restrict__ Wo,
                                               const float* __restrict__ bo,
                                               float* __restrict__ out) {
    const int b = blockIdx.x;
    const int tid = threadIdx.x;
    __shared__ float alpha[TT];
    __shared__ float red[128];

    if (tid < 32) {
        float e = g_e[b * TT + tid];
        float m = e;
#pragma unroll
        for (int o = 16; o > 0; o >>= 1) m = fmaxf(m, __shfl_xor_sync(0xffffffffu, m, o));
        float ex = __expf(e - m);
        float sum = ex;
#pragma unroll
        for (int o = 16; o > 0; o >>= 1) sum += __shfl_xor_sync(0xffffffffu, sum, o);
        alpha[tid] = ex / sum;
    }
    __syncthreads();

    float ctx = 0.f;
#pragma unroll 8
    for (int t = 0; t < TT; t++)
        ctx += alpha[t] * g_lstm_out[(b * TT + t) * DIN + tid];
    const float v = (ctx > 0.f) ? ctx : 0.5f * ctx;
    red[tid] = v * Wo[tid];
    __syncthreads();
#pragma unroll
    for (int s = 64; s > 0; s >>= 1) {
        if (tid < s) red[tid] += red[tid + s];
        __syncthreads();
    }
    if (tid == 0) out[b] = 1.f / (1.f + __expf(-(red[0] + bo[0])));
}

// =========================================================================
extern "C" void kernel_launch(void* const* d_in, const int* in_sizes, int n_in,
                              void* d_out, int out_size) {
    const float* x     = (const float*)d_in[0];
    // d_in[1] = visit_lens (int64) — unused by the reference math
    const float* emb   = (const float*)d_in[2];
    const float* Wg    = (const float*)d_in[3];
    const float* bg    = (const float*)d_in[4];
    const float* Wih_f = (const float*)d_in[5];
    const float* Whh_f = (const float*)d_in[6];
    const float* b_f   = (const float*)d_in[7];
    const float* Wih_b = (const float*)d_in[8];
    const float* Whh_b = (const float*)d_in[9];
    const float* b_b   = (const float*)d_in[10];
    const float* Wa    = (const float*)d_in[11];
    const float* ba    = (const float*)d_in[12];
    const float* ua    = (const float*)d_in[13];
    const float* Wo    = (const float*)d_in[14];
    const float* bo    = (const float*)d_in[15];
    float* out = (float*)d_out;

    k1_codes<<<dim3(TT, CSPLIT), 256>>>(x, emb);
    k2_prep<<<dim3(TT, 2), 512>>>(x, Wg, bg, Wih_f, b_f, Wih_b, b_b);
    k3_lstm<<<2, 512>>>(Whh_f, Whh_b);
    k4_attn<<<(BB * TT) / 4, 256>>>(Wa, ba, ua);
    k5_head<<<BB, 128>>>(Wo, bo, out);
}

// round 3
// speedup vs baseline: 1.3965x; 1.3965x over previous
#include <cuda_runtime.h>
#include <cstdint>

// Problem constants
#define BB 8
#define TT 32
#define CC 4880
#define DD 64
#define HH 64
#define AA 256
#define NG 256        // 4*H gate width
#define DIN 128       // 2*D
#define CSPLIT 8

// ---------------- scratch (device globals; no allocation) ----------------
__device__ float g_Spart[CSPLIT][TT][BB][DD];   // partial code sums
__device__ float g_CntPart[CSPLIT][TT][BB];     // partial nonzero counts
__device__ float g_Z[2][BB][TT][NG];            // input projections (dir, b, t, gate)
__device__ float g_lstm_out[BB * TT * 2 * HH];  // [b][t][128]
__device__ float g_e[BB * TT];                  // attention logits

// ---------------- math helpers ----------------
__device__ __forceinline__ float sigf(float x) {
    return 1.0f / (1.0f + __expf(-x));
}
__device__ __forceinline__ float tanhf_fast(float x) {
    return 1.0f - 2.0f / (__expf(2.0f * x) + 1.0f);
}

// =========================================================================
// K1: partial sums S[b,t,d] = sum_c x[b,t,c] * emb[c,d]  + count partials
// grid (32 t, 8 split), 256 threads (8 warps).
// =========================================================================
__global__ void __launch_bounds__(256) k1_codes(const float* __restrict__ x,
                                                const float* __restrict__ emb) {
    const int t = blockIdx.x, split = blockIdx.y;
    const int w = threadIdx.x >> 5, lane = threadIdx.x & 31;
    const int d0 = lane * 2;

    float acc[BB][2];
    float csum[BB];
#pragma unroll
    for (int b = 0; b < BB; b++) { acc[b][0] = 0.f; acc[b][1] = 0.f; csum[b] = 0.f; }

#pragma unroll 2
    for (int gi = split; gi * 32 < CC; gi += CSPLIT) {
        const int c0 = gi * 32 + w * 4;
        if (c0 < CC) {
            float2 e2[4];
#pragma unroll
            for (int ccx = 0; ccx < 4; ccx++)
                e2[ccx] = *(const float2*)&emb[(c0 + ccx) * DD + d0];
#pragma unroll
            for (int b = 0; b < BB; b++) {
                const float4 xv = *(const float4*)&x[(size_t)(b * TT + t) * CC + c0];
                acc[b][0] += xv.x * e2[0].x + xv.y * e2[1].x + xv.z * e2[2].x + xv.w * e2[3].x;
                acc[b][1] += xv.x * e2[0].y + xv.y * e2[1].y + xv.z * e2[2].y + xv.w * e2[3].y;
                csum[b] += (xv.x + xv.y) + (xv.z + xv.w);
            }
        }
    }

    __shared__ float2 wp[8][BB][DD / 2];
    __shared__ float cw[8][BB];
#pragma unroll
    for (int b = 0; b < BB; b++)
        wp[w][b][lane] = make_float2(acc[b][0], acc[b][1]);
    if (lane == 0) {
#pragma unroll
        for (int b = 0; b < BB; b++) cw[w][b] = csum[b];
    }
    __syncthreads();

    for (int o = threadIdx.x; o < BB * DD; o += 256) {
        const int b = o >> 6, d = o & 63;
        float s = 0.f;
#pragma unroll
        for (int ww = 0; ww < 8; ww++) {
            const float2 v = wp[ww][b][d >> 1];
            s += (d & 1) ? v.y : v.x;
        }
        g_Spart[split][t][b][d] = s;
    }
    if (threadIdx.x < BB) {
        float s = 0.f;
#pragma unroll
        for (int ww = 0; ww < 8; ww++) s += cw[ww][threadIdx.x];
        g_CntPart[split][t][threadIdx.x] = s;
    }
}

// =========================================================================
// K2: per t: counts, avg_xt, avg_ht, z projection for BOTH dirs
// grid (32 t), 512 threads.
// =========================================================================
__global__ void __launch_bounds__(512) k2_prep(const float* __restrict__ Wg,
                                               const float* __restrict__ bg,
                                               const float* __restrict__ Wih_f,
                                               const float* __restrict__ b_f,
                                               const float* __restrict__ Wih_b,
                                               const float* __restrict__ b_b) {
    const int t = blockIdx.x;
    const int tid = threadIdx.x;
    __shared__ float rows[BB][DIN];   // [b][0:64]=avg_ht, [64:128]=avg_xt
    __shared__ float cnt_sm[BB], has_sm[BB];

    // ---- counts from partials ----
    if (tid < BB) {
        float s = 0.f;
#pragma unroll
        for (int sp = 0; sp < CSPLIT; sp++) s += g_CntPart[sp][t][tid];
        cnt_sm[tid] = fmaxf(s, 1.f);
        has_sm[tid] = (s > 0.f) ? 1.f : 0.f;
    }
    __syncthreads();

    // ---- avg_xt: 512 outputs, one per thread ----
    {
        const int b = tid >> 6, d = tid & 63;
        float s = 0.f;
#pragma unroll
        for (int sp = 0; sp < CSPLIT; sp++) s += g_Spart[sp][t][b][d];
        rows[b][DD + d] = s / cnt_sm[b];
    }
    __syncthreads();

    // ---- avg_ht = avg_xt @ Wg + bg*has ----
    {
        const int b = tid >> 6, d = tid & 63;
        float a = bg[d] * has_sm[b];
#pragma unroll 16
        for (int k = 0; k < DD; k++) a += rows[b][DD + k] * Wg[k * DD + d];
        rows[b][d] = a;
    }
    __syncthreads();

    // ---- z = lstm_in @ Wih + bias : half block per dir ----
    const int dir = tid >> 8;
    const int tid2 = tid & 255;
    const float* __restrict__ Wih  = dir ? Wih_b : Wih_f;
    const float* __restrict__ bias = dir ? b_b : b_f;
    const int q = tid2 & 63, bg2 = tid2 >> 6;   // gate quad, b-pair index
    const int b0 = bg2 * 2;
    const float4 bv = *(const float4*)&bias[q * 4];
    float acc0[4] = {bv.x, bv.y, bv.z, bv.w};
    float acc1[4] = {bv.x, bv.y, bv.z, bv.w};
#pragma unroll 8
    for (int k = 0; k < DIN; k++) {
        const float4 wv = *(const float4*)&Wih[k * NG + q * 4];
        const float r0 = rows[b0][k];
        const float r1 = rows[b0 + 1][k];
        acc0[0] += r0 * wv.x; acc0[1] += r0 * wv.y; acc0[2] += r0 * wv.z; acc0[3] += r0 * wv.w;
        acc1[0] += r1 * wv.x; acc1[1] += r1 * wv.y; acc1[2] += r1 * wv.z; acc1[3] += r1 * wv.w;
    }
    *(float4*)&g_Z[dir][b0][t][q * 4]     = make_float4(acc0[0], acc0[1], acc0[2], acc0[3]);
    *(float4*)&g_Z[dir][b0 + 1][t][q * 4] = make_float4(acc1[0], acc1[1], acc1[2], acc1[3]);
}

// =========================================================================
// K3: bidirectional LSTM, split by (dir, batch). grid=16, 256 threads.
// Each block: 1-batch recurrence. Thread g owns gate column g of Whh
// (register-resident, k-paired for fma.f32x2); h broadcast via smem.
// =========================================================================
__global__ void __launch_bounds__(256, 1) k3_lstm(const float* __restrict__ Whh_f,
                                                  const float* __restrict__ Whh_b) {
    const int dir = blockIdx.x >> 3;
    const int b = blockIdx.x & 7;
    const float* __restrict__ Whh = dir ? Whh_b : Whh_f;
    __shared__ float h_sm[HH];
    __shared__ float z_sm[NG];
    const int g = threadIdx.x;

    // pack weight pairs (k, k+1) for gate column g
    unsigned long long wpk[32];
#pragma unroll
    for (int i = 0; i < 32; i++) {
        const float w0 = Whh[(2 * i) * NG + g];
        const float w1 = Whh[(2 * i + 1) * NG + g];
        asm("mov.b64 %0, {%1, %2};" : "=l"(wpk[i]) : "f"(w0), "f"(w1));
    }
    if (g < HH) h_sm[g] = 0.f;
    float cst = 0.f;   // cell state for threads g < 64
    __syncthreads();

    const float* __restrict__ zrow = &g_Z[dir][b][0][0];
    float* __restrict__ orow = &g_lstm_out[b * TT * (2 * HH) + dir * HH];

    for (int s = 0; s < TT; s++) {
        const int t = dir ? (TT - 1 - s) : s;
        const float zin = zrow[t * NG + g];
        unsigned long long acc = 0ull;
        const ulonglong2* hp = (const ulonglong2*)h_sm;
#pragma unroll
        for (int i = 0; i < 16; i++) {
            const ulonglong2 hhv = hp[i];
            asm("fma.rn.f32x2 %0, %1, %2, %0;" : "+l"(acc) : "l"(wpk[2 * i]), "l"(hhv.x));
            asm("fma.rn.f32x2 %0, %1, %2, %0;" : "+l"(acc) : "l"(wpk[2 * i + 1]), "l"(hhv.y));
        }
        float lo, hi;
        asm("mov.b64 {%0, %1}, %2;" : "=f"(lo), "=f"(hi) : "l"(acc));
        z_sm[g] = zin + lo + hi;
        __syncthreads();

        if (g < HH) {
            const float ziv = z_sm[g];
            const float zfv = z_sm[64 + g];
            const float zgv = z_sm[128 + g];
            const float zov = z_sm[192 + g];
            const float ig = sigf(ziv), fg = sigf(zfv);
            const float gg = tanhf_fast(zgv), og = sigf(zov);
            cst = fg * cst + ig * gg;
            const float hnew = og * tanhf_fast(cst);
            h_sm[g] = hnew;
            orow[t * (2 * HH) + g] = hnew;
        }
        __syncthreads();
    }
}

// =========================================================================
// K4: attention logits e[b,t] = tanh(row @ Wa + ba) . ua
// grid 32 (8 rows each), 256 threads. thread = (gate-quad q, row-pair)
// =========================================================================
__global__ void __launch_bounds__(256) k4_attn(const float* __restrict__ Wa,
                                               const float* __restrict__ ba,
                                               const float* __restrict__ ua) {
    const int bt0 = blockIdx.x * 8;
    const int tid = threadIdx.x;
    __shared__ float rows[8][DIN];
    __shared__ float red2[8][2];

    {
        const float4 v = *(const float4*)&g_lstm_out[bt0 * DIN + tid * 4];
        *(float4*)&rows[tid >> 5][(tid * 4) & 127] = v;
    }
    __syncthreads();

    const int q = tid & 63, rg = tid >> 6;   // gate quad, row-pair group
    const int r0 = rg * 2;
    const float4 bv = *(const float4*)&ba[q * 4];
    float acc0[4] = {bv.x, bv.y, bv.z, bv.w};
    float acc1[4] = {bv.x, bv.y, bv.z, bv.w};
#pragma unroll 8
    for (int k = 0; k < DIN; k++) {
        const float4 wv = *(const float4*)&Wa[k * AA + q * 4];
        const float v0 = rows[r0][k];
        const float v1 = rows[r0 + 1][k];
        acc0[0] += v0 * wv.x; acc0[1] += v0 * wv.y; acc0[2] += v0 * wv.z; acc0[3] += v0 * wv.w;
        acc1[0] += v1 * wv.x; acc1[1] += v1 * wv.y; acc1[2] += v1 * wv.z; acc1[3] += v1 * wv.w;
    }
    const float4 uav = *(const float4*)&ua[q * 4];
    float p0 = tanhf_fast(acc0[0]) * uav.x + tanhf_fast(acc0[1]) * uav.y
             + tanhf_fast(acc0[2]) * uav.z + tanhf_fast(acc0[3]) * uav.w;
    float p1 = tanhf_fast(acc1[0]) * uav.x + tanhf_fast(acc1[1]) * uav.y
             + tanhf_fast(acc1[2]) * uav.z + tanhf_fast(acc1[3]) * uav.w;
#pragma unroll
    for (int o = 16; o > 0; o >>= 1) {
        p0 += __shfl_down_sync(0xffffffffu, p0, o);
        p1 += __shfl_down_sync(0xffffffffu, p1, o);
    }
    const int w = tid >> 5;       // warps (rg*2, rg*2+1) cover the same row-pair
    if ((tid & 31) == 0) {
        red2[w][0] = p0;
        red2[w][1] = p1;
    }
    __syncthreads();
    if (tid < 8) {
        const int rg2 = tid >> 1, i = tid & 1;
        g_e[bt0 + rg2 * 2 + i] = red2[rg2 * 2][i] + red2[rg2 * 2 + 1][i];
    }
}

// =========================================================================
// K5: softmax over t, context, leaky_relu, output head. grid 8 (b), 128 thr.
// =========================================================================
__global__ void __launch_bounds__(128) k5_head(const float* __restrict__ Wo,
                                               const float* __restrict__ bo,
                                               float* __restrict__ out) {
    const int b = blockIdx.x;
    const int tid = threadIdx.x;
    __shared__ float alpha[TT];
    __shared__ float red[128];

    if (tid < 32) {
        float e = g_e[b * TT + tid];
        float m = e;
#pragma unroll
        for (int o = 16; o > 0; o >>= 1) m = fmaxf(m, __shfl_xor_sync(0xffffffffu, m, o));
        float ex = __expf(e - m);
        float sum = ex;
#pragma unroll
        for (int o = 16; o > 0; o >>= 1) sum += __shfl_xor_sync(0xffffffffu, sum, o);
        alpha[tid] = ex / sum;
    }
    __syncthreads();

    float ctx = 0.f;
#pragma unroll 8
    for (int t = 0; t < TT; t++)
        ctx += alpha[t] * g_lstm_out[(b * TT + t) * DIN + tid];
    const float v = (ctx > 0.f) ? ctx : 0.5f * ctx;
    red[tid] = v * Wo[tid];
    __syncthreads();
#pragma unroll
    for (int s = 64; s > 0; s >>= 1) {
        if (tid < s) red[tid] += red[tid + s];
        __syncthreads();
    }
    if (tid == 0) out[b] = 1.f / (1.f + __expf(-(red[0] + bo[0])));
}

// =========================================================================
extern "C" void kernel_launch(void* const* d_in, const int* in_sizes, int n_in,
                              void* d_out, int out_size) {
    const float* x     = (const float*)d_in[0];
    // d_in[1] = visit_lens (int64) — unused by the reference math
    const float* emb   = (const float*)d_in[2];
    const float* Wg    = (const float*)d_in[3];
    const float* bg    = (const float*)d_in[4];
    const float* Wih_f = (const float*)d_in[5];
    const float* Whh_f = (const float*)d_in[6];
    const float* b_f   = (const float*)d_in[7];
    const float* Wih_b = (const float*)d_in[8];
    const float* Whh_b = (const float*)d_in[9];
    const float* b_b   = (const float*)d_in[10];
    const float* Wa    = (const float*)d_in[11];
    const float* ba    = (const float*)d_in[12];
    const float* ua    = (const float*)d_in[13];
    const float* Wo    = (const float*)d_in[14];
    const float* bo    = (const float*)d_in[15];
    float* out = (float*)d_out;

    k1_codes<<<dim3(TT, CSPLIT), 256>>>(x, emb);
    k2_prep<<<TT, 512>>>(Wg, bg, Wih_f, b_f, Wih_b, b_b);
    k3_lstm<<<16, 256>>>(Whh_f, Whh_b);
    k4_attn<<<BB * TT / 8, 256>>>(Wa, ba, ua);
    k5_head<<<BB, 128>>>(Wo, bo, out);
}

// round 6
// speedup vs baseline: 1.5404x; 1.1030x over previous
#include <cuda_runtime.h>
#include <cstdint>

// Problem constants
#define BB 8
#define TT 32
#define CC 4880
#define DD 64
#define HH 64
#define AA 256
#define NG 256        // 4*H gate width
#define DIN 128       // 2*D
#define CSPLIT 8

// ---------------- scratch (device globals; no allocation) ----------------
__device__ float g_Spart[CSPLIT][TT][BB][DD];   // partial code sums
__device__ float g_CntPart[CSPLIT][TT][BB];     // partial nonzero counts
__device__ float g_Z[2][BB][TT][NG];            // input projections (dir, b, t, gate)
__device__ float g_lstm_out[BB * TT * 2 * HH];  // [b][t][128]

// ---------------- math helpers ----------------
__device__ __forceinline__ float sigf(float x) {
    return 1.0f / (1.0f + __expf(-x));
}
__device__ __forceinline__ float tanhf_fast(float x) {
    return 1.0f - 2.0f / (__expf(2.0f * x) + 1.0f);
}

// =========================================================================
// K1: partial sums S[b,t,d] = sum_c x[b,t,c] * emb[c,d]  + count partials
// grid (32 t, 8 split), 256 threads (8 warps).
// =========================================================================
__global__ void __launch_bounds__(256) k1_codes(const float* __restrict__ x,
                                                const float* __restrict__ emb) {
    const int t = blockIdx.x, split = blockIdx.y;
    const int w = threadIdx.x >> 5, lane = threadIdx.x & 31;
    const int d0 = lane * 2;

    float acc[BB][2];
    float csum[BB];
#pragma unroll
    for (int b = 0; b < BB; b++) { acc[b][0] = 0.f; acc[b][1] = 0.f; csum[b] = 0.f; }

#pragma unroll 2
    for (int gi = split; gi * 32 < CC; gi += CSPLIT) {
        const int c0 = gi * 32 + w * 4;
        if (c0 < CC) {
            float2 e2[4];
#pragma unroll
            for (int ccx = 0; ccx < 4; ccx++)
                e2[ccx] = *(const float2*)&emb[(c0 + ccx) * DD + d0];
#pragma unroll
            for (int b = 0; b < BB; b++) {
                const float4 xv = *(const float4*)&x[(size_t)(b * TT + t) * CC + c0];
                acc[b][0] += xv.x * e2[0].x + xv.y * e2[1].x + xv.z * e2[2].x + xv.w * e2[3].x;
                acc[b][1] += xv.x * e2[0].y + xv.y * e2[1].y + xv.z * e2[2].y + xv.w * e2[3].y;
                csum[b] += (xv.x + xv.y) + (xv.z + xv.w);
            }
        }
    }

    __shared__ float2 wp[8][BB][DD / 2];
    __shared__ float cw[8][BB];
#pragma unroll
    for (int b = 0; b < BB; b++)
        wp[w][b][lane] = make_float2(acc[b][0], acc[b][1]);
    if (lane == 0) {
#pragma unroll
        for (int b = 0; b < BB; b++) cw[w][b] = csum[b];
    }
    __syncthreads();

    for (int o = threadIdx.x; o < BB * DD; o += 256) {
        const int b = o >> 6, d = o & 63;
        float s = 0.f;
#pragma unroll
        for (int ww = 0; ww < 8; ww++) {
            const float2 v = wp[ww][b][d >> 1];
            s += (d & 1) ? v.y : v.x;
        }
        g_Spart[split][t][b][d] = s;
    }
    if (threadIdx.x < BB) {
        float s = 0.f;
#pragma unroll
        for (int ww = 0; ww < 8; ww++) s += cw[ww][threadIdx.x];
        g_CntPart[split][t][threadIdx.x] = s;
    }
}

// =========================================================================
// K2: per t: counts, avg_xt, avg_ht, z projection. grid 32, 512 threads.
// One 16KB staging buffer reused: phase A holds Wg, phase B holds Wih
// chunks (8 k-rows per dir per chunk).
// =========================================================================
__global__ void __launch_bounds__(512) k2_prep(const float* __restrict__ Wg,
                                               const float* __restrict__ bg,
                                               const float* __restrict__ Wih_f,
                                               const float* __restrict__ b_f,
                                               const float* __restrict__ Wih_b,
                                               const float* __restrict__ b_b) {
    const int t = blockIdx.x;
    const int tid = threadIdx.x;
    __shared__ float rows[BB][DIN];     // [b][0:64]=avg_ht, [64:128]=avg_xt
    __shared__ float4 wbuf[1024];       // 16KB staging (Wg, then Wih chunks)
    __shared__ float cnt_sm[BB], has_sm[BB];

    // ---- stage Wg into wbuf (64x64 floats == 1024 float4) ----
    {
        const float4* src = (const float4*)Wg;
        wbuf[tid] = src[tid];
        wbuf[tid + 512] = src[tid + 512];
    }
    // ---- counts from partials ----
    if (tid < BB) {
        float s = 0.f;
#pragma unroll
        for (int sp = 0; sp < CSPLIT; sp++) s += g_CntPart[sp][t][tid];
        cnt_sm[tid] = fmaxf(s, 1.f);
        has_sm[tid] = (s > 0.f) ? 1.f : 0.f;
    }
    __syncthreads();

    // ---- avg_xt: 512 outputs, one per thread ----
    {
        const int b = tid >> 6, d = tid & 63;
        float s = 0.f;
#pragma unroll
        for (int sp = 0; sp < CSPLIT; sp++) s += g_Spart[sp][t][b][d];
        rows[b][DD + d] = s / cnt_sm[b];
    }
    __syncthreads();

    // ---- avg_ht = avg_xt @ Wg + bg*has (Wg from wbuf) ----
    {
        const int b = tid >> 6, d = tid & 63;
        const float* wg_sm = (const float*)wbuf;
        float a = bg[d] * has_sm[b];
#pragma unroll 16
        for (int k = 0; k < DD; k++) a += rows[b][DD + k] * wg_sm[k * DD + d];
        rows[b][d] = a;
    }
    __syncthreads();

    // ---- z = lstm_in @ Wih + bias : half block per dir ----
    // wbuf reused per chunk as [dir][8 k-rows][64 quads]
    const int dir = tid >> 8;
    const int tid2 = tid & 255;
    const float* __restrict__ Wih  = dir ? Wih_b : Wih_f;
    const float* __restrict__ bias = dir ? b_b : b_f;
    const int q = tid2 & 63, bg2 = tid2 >> 6;   // gate quad, b-pair index
    const int b0 = bg2 * 2;
    const float4 bv = *(const float4*)&bias[q * 4];
    float acc0[4] = {bv.x, bv.y, bv.z, bv.w};
    float acc1[4] = {bv.x, bv.y, bv.z, bv.w};

    for (int ch = 0; ch < 16; ch++) {
        // stage Wih rows [ch*8, ch*8+8) for this dir: 512 float4 / 256 thr
        {
            const float4* wsrc = (const float4*)&Wih[ch * 8 * NG];
            float4* wdst = &wbuf[dir * 512];
            wdst[tid2] = wsrc[tid2];
            wdst[tid2 + 256] = wsrc[tid2 + 256];
        }
        __syncthreads();
#pragma unroll
        for (int kk = 0; kk < 8; kk++) {
            const float4 wv = wbuf[dir * 512 + kk * 64 + q];
            const int k = ch * 8 + kk;
            const float r0 = rows[b0][k];
            const float r1 = rows[b0 + 1][k];
            acc0[0] += r0 * wv.x; acc0[1] += r0 * wv.y; acc0[2] += r0 * wv.z; acc0[3] += r0 * wv.w;
            acc1[0] += r1 * wv.x; acc1[1] += r1 * wv.y; acc1[2] += r1 * wv.z; acc1[3] += r1 * wv.w;
        }
        __syncthreads();
    }
    *(float4*)&g_Z[dir][b0][t][q * 4]     = make_float4(acc0[0], acc0[1], acc0[2], acc0[3]);
    *(float4*)&g_Z[dir][b0 + 1][t][q * 4] = make_float4(acc1[0], acc1[1], acc1[2], acc1[3]);
}

// =========================================================================
// K3: bidirectional LSTM, split by (dir, batch). grid=16, 256 threads.
// Thread g owns gate column g of Whh (register-resident, k-paired f32x2);
// h broadcast via smem; z input prefetched one step ahead.
// =========================================================================
__global__ void __launch_bounds__(256, 1) k3_lstm(const float* __restrict__ Whh_f,
                                                  const float* __restrict__ Whh_b) {
    const int dir = blockIdx.x >> 3;
    const int b = blockIdx.x & 7;
    const float* __restrict__ Whh = dir ? Whh_b : Whh_f;
    __shared__ float h_sm[HH];
    __shared__ float z_sm[NG];
    const int g = threadIdx.x;

    unsigned long long wpk[32];
#pragma unroll
    for (int i = 0; i < 32; i++) {
        const float w0 = Whh[(2 * i) * NG + g];
        const float w1 = Whh[(2 * i + 1) * NG + g];
        asm("mov.b64 %0, {%1, %2};" : "=l"(wpk[i]) : "f"(w0), "f"(w1));
    }
    if (g < HH) h_sm[g] = 0.f;
    float cst = 0.f;
    __syncthreads();

    const float* __restrict__ zrow = &g_Z[dir][b][0][0];
    float* __restrict__ orow = &g_lstm_out[b * TT * (2 * HH) + dir * HH];

    const int t0 = dir ? (TT - 1) : 0;
    float zcur = zrow[t0 * NG + g];

    for (int s = 0; s < TT; s++) {
        const int t = dir ? (TT - 1 - s) : s;
        float znext = 0.f;
        if (s + 1 < TT) {
            const int tn = dir ? (TT - 2 - s) : (s + 1);
            znext = zrow[tn * NG + g];
        }
        unsigned long long acc = 0ull;
        const ulonglong2* hp = (const ulonglong2*)h_sm;
#pragma unroll
        for (int i = 0; i < 16; i++) {
            const ulonglong2 hhv = hp[i];
            asm("fma.rn.f32x2 %0, %1, %2, %0;" : "+l"(acc) : "l"(wpk[2 * i]), "l"(hhv.x));
            asm("fma.rn.f32x2 %0, %1, %2, %0;" : "+l"(acc) : "l"(wpk[2 * i + 1]), "l"(hhv.y));
        }
        float lo, hi;
        asm("mov.b64 {%0, %1}, %2;" : "=f"(lo), "=f"(hi) : "l"(acc));
        z_sm[g] = zcur + lo + hi;
        __syncthreads();

        if (g < HH) {
            const float ziv = z_sm[g];
            const float zfv = z_sm[64 + g];
            const float zgv = z_sm[128 + g];
            const float zov = z_sm[192 + g];
            const float ig = sigf(ziv), fg = sigf(zfv);
            const float gg = tanhf_fast(zgv), og = sigf(zov);
            cst = fg * cst + ig * gg;
            const float hnew = og * tanhf_fast(cst);
            h_sm[g] = hnew;
            orow[t * (2 * HH) + g] = hnew;
        }
        __syncthreads();
        zcur = znext;
    }
}

// =========================================================================
// K45: fused attention + softmax + head. grid 8 (one block per batch),
// 512 threads. Wa staged through smem in 16-row chunks (guaranteed MLP).
// =========================================================================
__global__ void __launch_bounds__(512) k45_attn_head(const float* __restrict__ Wa,
                                                     const float* __restrict__ ba,
                                                     const float* __restrict__ ua,
                                                     const float* __restrict__ Wo,
                                                     const float* __restrict__ bo,
                                                     float* __restrict__ out) {
    const int b = blockIdx.x;
    const int tid = threadIdx.x;
    const int q = tid & 63;       // col quad (global cols q*4..q*4+3)
    const int rg = tid >> 6;      // 0..7 -> rows rg*4..rg*4+3 (t values)
    __shared__ float rows[TT][DIN];        // 16KB lstm_out for this b
    __shared__ float4 wbuf[16][DD];        // 16KB Wa chunk [k][quad]
    __shared__ float red[16][4];           // warp partials
    __shared__ float alpha[TT];
    __shared__ float cred[4][DIN];

    // stage lstm_out rows: 1024 float4 / 512 threads
    {
        const float4* src = (const float4*)&g_lstm_out[b * TT * DIN];
        float4* dst = (float4*)rows;
        dst[tid] = src[tid];
        dst[tid + 512] = src[tid + 512];
    }
    const float4 bav = *(const float4*)&ba[q * 4];
    float acc[4][4];
#pragma unroll
    for (int r = 0; r < 4; r++) {
        acc[r][0] = bav.x; acc[r][1] = bav.y; acc[r][2] = bav.z; acc[r][3] = bav.w;
    }
    __syncthreads();

    for (int ch = 0; ch < 8; ch++) {
        // stage Wa rows [ch*16, ch*16+16): 1024 float4 / 512 threads
        {
            const float4* wsrc = (const float4*)&Wa[ch * 16 * AA];
            float4* wdst = (float4*)wbuf;
            wdst[tid] = wsrc[tid];
            wdst[tid + 512] = wsrc[tid + 512];
        }
        __syncthreads();
#pragma unroll
        for (int kk = 0; kk < 16; kk++) {
            const float4 wv = wbuf[kk][q];
            const int k = ch * 16 + kk;
#pragma unroll
            for (int r = 0; r < 4; r++) {
                const float v = rows[rg * 4 + r][k];
                acc[r][0] += v * wv.x; acc[r][1] += v * wv.y;
                acc[r][2] += v * wv.z; acc[r][3] += v * wv.w;
            }
        }
        __syncthreads();
    }

    // tanh + dot with ua quad
    const float4 uav = *(const float4*)&ua[q * 4];
    float p[4];
#pragma unroll
    for (int r = 0; r < 4; r++) {
        p[r] = tanhf_fast(acc[r][0]) * uav.x + tanhf_fast(acc[r][1]) * uav.y
             + tanhf_fast(acc[r][2]) * uav.z + tanhf_fast(acc[r][3]) * uav.w;
    }
#pragma unroll
    for (int o = 16; o > 0; o >>= 1) {
#pragma unroll
        for (int r = 0; r < 4; r++) p[r] += __shfl_down_sync(0xffffffffu, p[r], o);
    }
    const int wid = tid >> 5;    // 16 warps; warps (2*rg, 2*rg+1) share rows
    if ((tid & 31) == 0) {
#pragma unroll
        for (int r = 0; r < 4; r++) red[wid][r] = p[r];
    }
    __syncthreads();

    // softmax over the 32 t's in one warp
    if (tid < TT) {
        const int trg = tid >> 2, r = tid & 3;
        float e = red[trg * 2][r] + red[trg * 2 + 1][r];
        float m = e;
#pragma unroll
        for (int o = 16; o > 0; o >>= 1) m = fmaxf(m, __shfl_xor_sync(0xffffffffu, m, o));
        const float ex = __expf(e - m);
        float sum = ex;
#pragma unroll
        for (int o = 16; o > 0; o >>= 1) sum += __shfl_xor_sync(0xffffffffu, sum, o);
        alpha[tid] = ex / sum;
    }
    __syncthreads();

    // context: col = tid&127, t-quarter = tid>>7
    {
        const int col = tid & 127, grp = tid >> 7;
        float part = 0.f;
#pragma unroll
        for (int i = 0; i < 8; i++) {
            const int tt2 = grp * 8 + i;
            part += alpha[tt2] * rows[tt2][col];
        }
        cred[grp][col] = part;
    }
    __syncthreads();
    if (tid < DIN) {
        const float ctx = cred[0][tid] + cred[1][tid] + cred[2][tid] + cred[3][tid];
        const float v = (ctx > 0.f) ? ctx : 0.5f * ctx;
        cred[0][tid] = v * Wo[tid];
    }
    __syncthreads();
    if (tid < 64) cred[0][tid] += cred[0][tid + 64];
    __syncthreads();
    if (tid < 32) {
        float s = cred[0][tid] + cred[0][tid + 32];
#pragma unroll
        for (int o = 16; o > 0; o >>= 1) s += __shfl_down_sync(0xffffffffu, s, o);
        if (tid == 0) out[b] = 1.f / (1.f + __expf(-(s + bo[0])));
    }
}

// =========================================================================
extern "C" void kernel_launch(void* const* d_in, const int* in_sizes, int n_in,
                              void* d_out, int out_size) {
    const float* x     = (const float*)d_in[0];
    // d_in[1] = visit_lens (int64) — unused by the reference math
    const float* emb   = (const float*)d_in[2];
    const float* Wg    = (const float*)d_in[3];
    const float* bg    = (const float*)d_in[4];
    const float* Wih_f = (const float*)d_in[5];
    const float* Whh_f = (const float*)d_in[6];
    const float* b_f   = (const float*)d_in[7];
    const float* Wih_b = (const float*)d_in[8];
    const float* Whh_b = (const float*)d_in[9];
    const float* b_b   = (const float*)d_in[10];
    const float* Wa    = (const float*)d_in[11];
    const float* ba    = (const float*)d_in[12];
    const float* ua    = (const float*)d_in[13];
    const float* Wo    = (const float*)d_in[14];
    const float* bo    = (const float*)d_in[15];
    float* out = (float*)d_out;

    k1_codes<<<dim3(TT, CSPLIT), 256>>>(x, emb);
    k2_prep<<<TT, 512>>>(Wg, bg, Wih_f, b_f, Wih_b, b_b);
    k3_lstm<<<16, 256>>>(Whh_f, Whh_b);
    k45_attn_head<<<BB, 512>>>(Wa, ba, ua, Wo, bo, out);
}

// round 8
// speedup vs baseline: 1.6022x; 1.0401x over previous
#include <cuda_runtime.h>
#include <cstdint>

// Problem constants
#define BB 8
#define TT 32
#define CC 4880
#define DD 64
#define HH 64
#define AA 256
#define NG 256        // 4*H gate width
#define DIN 128       // 2*D
#define CSPLIT 8

// ---------------- scratch (device globals; no allocation) ----------------
__device__ float g_Spart[CSPLIT][TT][BB][DD];   // partial code sums
__device__ float g_CntPart[CSPLIT][TT][BB];     // partial nonzero counts
__device__ float g_Z[2][BB][TT][NG];            // input projections (dir, b, t, gate)
__device__ float g_lstm_out[BB * TT * 2 * HH];  // [b][t][128]
__device__ float g_e[BB * TT];                  // attention logits

// ---------------- math helpers ----------------
__device__ __forceinline__ float sigf(float x) {
    return 1.0f / (1.0f + __expf(-x));
}
__device__ __forceinline__ float tanhf_fast(float x) {
    return 1.0f - 2.0f / (__expf(2.0f * x) + 1.0f);
}

// =========================================================================
// K1: partial sums S[b,t,d] = sum_c x[b,t,c] * emb[c,d]  + count partials
// grid (32 t, 8 split), 256 threads (8 warps).
// =========================================================================
__global__ void __launch_bounds__(256) k1_codes(const float* __restrict__ x,
                                                const float* __restrict__ emb) {
    const int t = blockIdx.x, split = blockIdx.y;
    const int w = threadIdx.x >> 5, lane = threadIdx.x & 31;
    const int d0 = lane * 2;

    float acc[BB][2];
    float csum[BB];
#pragma unroll
    for (int b = 0; b < BB; b++) { acc[b][0] = 0.f; acc[b][1] = 0.f; csum[b] = 0.f; }

#pragma unroll 2
    for (int gi = split; gi * 32 < CC; gi += CSPLIT) {
        const int c0 = gi * 32 + w * 4;
        if (c0 < CC) {
            float2 e2[4];
#pragma unroll
            for (int ccx = 0; ccx < 4; ccx++)
                e2[ccx] = *(const float2*)&emb[(c0 + ccx) * DD + d0];
#pragma unroll
            for (int b = 0; b < BB; b++) {
                const float4 xv = *(const float4*)&x[(size_t)(b * TT + t) * CC + c0];
                acc[b][0] += xv.x * e2[0].x + xv.y * e2[1].x + xv.z * e2[2].x + xv.w * e2[3].x;
                acc[b][1] += xv.x * e2[0].y + xv.y * e2[1].y + xv.z * e2[2].y + xv.w * e2[3].y;
                csum[b] += (xv.x + xv.y) + (xv.z + xv.w);
            }
        }
    }

    __shared__ float2 wp[8][BB][DD / 2];
    __shared__ float cw[8][BB];
#pragma unroll
    for (int b = 0; b < BB; b++)
        wp[w][b][lane] = make_float2(acc[b][0], acc[b][1]);
    if (lane == 0) {
#pragma unroll
        for (int b = 0; b < BB; b++) cw[w][b] = csum[b];
    }
    __syncthreads();

    for (int o = threadIdx.x; o < BB * DD; o += 256) {
        const int b = o >> 6, d = o & 63;
        float s = 0.f;
#pragma unroll
        for (int ww = 0; ww < 8; ww++) {
            const float2 v = wp[ww][b][d >> 1];
            s += (d & 1) ? v.y : v.x;
        }
        g_Spart[split][t][b][d] = s;
    }
    if (threadIdx.x < BB) {
        float s = 0.f;
#pragma unroll
        for (int ww = 0; ww < 8; ww++) s += cw[ww][threadIdx.x];
        g_CntPart[split][t][threadIdx.x] = s;
    }
}

// =========================================================================
// K2: per t: counts, avg_xt, avg_ht, z projection. grid 32, 512 threads.
// One 16KB staging buffer reused: phase A holds Wg, phase B holds Wih
// chunks (8 k-rows per dir per chunk).
// =========================================================================
__global__ void __launch_bounds__(512) k2_prep(const float* __restrict__ Wg,
                                               const float* __restrict__ bg,
                                               const float* __restrict__ Wih_f,
                                               const float* __restrict__ b_f,
                                               const float* __restrict__ Wih_b,
                                               const float* __restrict__ b_b) {
    const int t = blockIdx.x;
    const int tid = threadIdx.x;
    __shared__ float rows[BB][DIN];     // [b][0:64]=avg_ht, [64:128]=avg_xt
    __shared__ float4 wbuf[1024];       // 16KB staging (Wg, then Wih chunks)
    __shared__ float cnt_sm[BB], has_sm[BB];

    // ---- stage Wg into wbuf (64x64 floats == 1024 float4) ----
    {
        const float4* src = (const float4*)Wg;
        wbuf[tid] = src[tid];
        wbuf[tid + 512] = src[tid + 512];
    }
    // ---- counts from partials ----
    if (tid < BB) {
        float s = 0.f;
#pragma unroll
        for (int sp = 0; sp < CSPLIT; sp++) s += g_CntPart[sp][t][tid];
        cnt_sm[tid] = fmaxf(s, 1.f);
        has_sm[tid] = (s > 0.f) ? 1.f : 0.f;
    }
    __syncthreads();

    // ---- avg_xt: 512 outputs, one per thread ----
    {
        const int b = tid >> 6, d = tid & 63;
        float s = 0.f;
#pragma unroll
        for (int sp = 0; sp < CSPLIT; sp++) s += g_Spart[sp][t][b][d];
        rows[b][DD + d] = s / cnt_sm[b];
    }
    __syncthreads();

    // ---- avg_ht = avg_xt @ Wg + bg*has (Wg from wbuf) ----
    {
        const int b = tid >> 6, d = tid & 63;
        const float* wg_sm = (const float*)wbuf;
        float a = bg[d] * has_sm[b];
#pragma unroll 16
        for (int k = 0; k < DD; k++) a += rows[b][DD + k] * wg_sm[k * DD + d];
        rows[b][d] = a;
    }
    __syncthreads();

    // ---- z = lstm_in @ Wih + bias : half block per dir ----
    // wbuf reused per chunk as [dir][8 k-rows][64 quads]
    const int dir = tid >> 8;
    const int tid2 = tid & 255;
    const float* __restrict__ Wih  = dir ? Wih_b : Wih_f;
    const float* __restrict__ bias = dir ? b_b : b_f;
    const int q = tid2 & 63, bg2 = tid2 >> 6;   // gate quad, b-pair index
    const int b0 = bg2 * 2;
    const float4 bv = *(const float4*)&bias[q * 4];
    float acc0[4] = {bv.x, bv.y, bv.z, bv.w};
    float acc1[4] = {bv.x, bv.y, bv.z, bv.w};

    for (int ch = 0; ch < 16; ch++) {
        // stage Wih rows [ch*8, ch*8+8) for this dir: 512 float4 / 256 thr
        {
            const float4* wsrc = (const float4*)&Wih[ch * 8 * NG];
            float4* wdst = &wbuf[dir * 512];
            wdst[tid2] = wsrc[tid2];
            wdst[tid2 + 256] = wsrc[tid2 + 256];
        }
        __syncthreads();
#pragma unroll
        for (int kk = 0; kk < 8; kk++) {
            const float4 wv = wbuf[dir * 512 + kk * 64 + q];
            const int k = ch * 8 + kk;
            const float r0 = rows[b0][k];
            const float r1 = rows[b0 + 1][k];
            acc0[0] += r0 * wv.x; acc0[1] += r0 * wv.y; acc0[2] += r0 * wv.z; acc0[3] += r0 * wv.w;
            acc1[0] += r1 * wv.x; acc1[1] += r1 * wv.y; acc1[2] += r1 * wv.z; acc1[3] += r1 * wv.w;
        }
        __syncthreads();
    }
    *(float4*)&g_Z[dir][b0][t][q * 4]     = make_float4(acc0[0], acc0[1], acc0[2], acc0[3]);
    *(float4*)&g_Z[dir][b0 + 1][t][q * 4] = make_float4(acc1[0], acc1[1], acc1[2], acc1[3]);
}

// =========================================================================
// K3: bidirectional LSTM, split by (dir, batch). grid=16, 256 threads.
// Thread g owns gate column g of Whh (register-resident, k-paired f32x2);
// h broadcast via smem; z input prefetched one step ahead.
// =========================================================================
__global__ void __launch_bounds__(256, 1) k3_lstm(const float* __restrict__ Whh_f,
                                                  const float* __restrict__ Whh_b) {
    const int dir = blockIdx.x >> 3;
    const int b = blockIdx.x & 7;
    const float* __restrict__ Whh = dir ? Whh_b : Whh_f;
    __shared__ float h_sm[HH];
    __shared__ float z_sm[NG];
    const int g = threadIdx.x;

    unsigned long long wpk[32];
#pragma unroll
    for (int i = 0; i < 32; i++) {
        const float w0 = Whh[(2 * i) * NG + g];
        const float w1 = Whh[(2 * i + 1) * NG + g];
        asm("mov.b64 %0, {%1, %2};" : "=l"(wpk[i]) : "f"(w0), "f"(w1));
    }
    if (g < HH) h_sm[g] = 0.f;
    float cst = 0.f;
    __syncthreads();

    const float* __restrict__ zrow = &g_Z[dir][b][0][0];
    float* __restrict__ orow = &g_lstm_out[b * TT * (2 * HH) + dir * HH];

    const int t0 = dir ? (TT - 1) : 0;
    float zcur = zrow[t0 * NG + g];

    for (int s = 0; s < TT; s++) {
        const int t = dir ? (TT - 1 - s) : s;
        float znext = 0.f;
        if (s + 1 < TT) {
            const int tn = dir ? (TT - 2 - s) : (s + 1);
            znext = zrow[tn * NG + g];
        }
        unsigned long long acc = 0ull;
        const ulonglong2* hp = (const ulonglong2*)h_sm;
#pragma unroll
        for (int i = 0; i < 16; i++) {
            const ulonglong2 hhv = hp[i];
            asm("fma.rn.f32x2 %0, %1, %2, %0;" : "+l"(acc) : "l"(wpk[2 * i]), "l"(hhv.x));
            asm("fma.rn.f32x2 %0, %1, %2, %0;" : "+l"(acc) : "l"(wpk[2 * i + 1]), "l"(hhv.y));
        }
        float lo, hi;
        asm("mov.b64 {%0, %1}, %2;" : "=f"(lo), "=f"(hi) : "l"(acc));
        z_sm[g] = zcur + lo + hi;
        __syncthreads();

        if (g < HH) {
            const float ziv = z_sm[g];
            const float zfv = z_sm[64 + g];
            const float zgv = z_sm[128 + g];
            const float zov = z_sm[192 + g];
            const float ig = sigf(ziv), fg = sigf(zfv);
            const float gg = tanhf_fast(zgv), og = sigf(zov);
            cst = fg * cst + ig * gg;
            const float hnew = og * tanhf_fast(cst);
            h_sm[g] = hnew;
            orow[t * (2 * HH) + g] = hnew;
        }
        __syncthreads();
        zcur = znext;
    }
}

// =========================================================================
// K4: attention logits e[b,t] = tanh(row @ Wa + ba) . ua
// grid 64 (4 rows each), 256 threads. Wa smem-staged in 16-row chunks.
// thread = (col quad q, row rg).
// =========================================================================
__global__ void __launch_bounds__(256) k4_attn(const float* __restrict__ Wa,
                                               const float* __restrict__ ba,
                                               const float* __restrict__ ua) {
    const int bt0 = blockIdx.x * 4;
    const int tid = threadIdx.x;
    const int q = tid & 63;       // col quad (cols q*4..q*4+3)
    const int rg = tid >> 6;      // row 0..3
    __shared__ float rows[4][DIN];        // 2KB
    __shared__ float4 wbuf[16][DD];       // 16KB Wa chunk [k][quad]
    __shared__ float red[8];              // per-warp partials

    // stage 4 rows (512 floats = 128 float4)
    if (tid < 128) {
        ((float4*)rows)[tid] = ((const float4*)&g_lstm_out[bt0 * DIN])[tid];
    }
    const float4 bav = *(const float4*)&ba[q * 4];
    float acc0 = bav.x, acc1 = bav.y, acc2 = bav.z, acc3 = bav.w;
    __syncthreads();

    for (int ch = 0; ch < 8; ch++) {
        // stage Wa rows [ch*16, ch*16+16): 1024 float4 / 256 threads
        {
            const float4* wsrc = (const float4*)&Wa[ch * 16 * AA];
            float4* wdst = (float4*)wbuf;
#pragma unroll
            for (int i = 0; i < 4; i++)
                wdst[tid + i * 256] = wsrc[tid + i * 256];
        }
        __syncthreads();
#pragma unroll
        for (int kk = 0; kk < 16; kk++) {
            const float4 wv = wbuf[kk][q];
            const float v = rows[rg][ch * 16 + kk];
            acc0 += v * wv.x; acc1 += v * wv.y; acc2 += v * wv.z; acc3 += v * wv.w;
        }
        __syncthreads();
    }

    const float4 uav = *(const float4*)&ua[q * 4];
    float p = tanhf_fast(acc0) * uav.x + tanhf_fast(acc1) * uav.y
            + tanhf_fast(acc2) * uav.z + tanhf_fast(acc3) * uav.w;
#pragma unroll
    for (int o = 16; o > 0; o >>= 1) p += __shfl_down_sync(0xffffffffu, p, o);
    const int wid = tid >> 5;   // warps (2*rg, 2*rg+1) cover row rg
    if ((tid & 31) == 0) red[wid] = p;
    __syncthreads();
    if (tid < 4) g_e[bt0 + tid] = red[tid * 2] + red[tid * 2 + 1];
}

// =========================================================================
// K5: softmax over t, context, leaky_relu, output head. grid 8 (b), 128 thr.
// =========================================================================
__global__ void __launch_bounds__(128) k5_head(const float* __restrict__ Wo,
                                               const float* __restrict__ bo,
                                               float* __restrict__ out) {
    const int b = blockIdx.x;
    const int tid = threadIdx.x;
    __shared__ float alpha[TT];
    __shared__ float red[128];

    if (tid < 32) {
        float e = g_e[b * TT + tid];
        float m = e;
#pragma unroll
        for (int o = 16; o > 0; o >>= 1) m = fmaxf(m, __shfl_xor_sync(0xffffffffu, m, o));
        float ex = __expf(e - m);
        float sum = ex;
#pragma unroll
        for (int o = 16; o > 0; o >>= 1) sum += __shfl_xor_sync(0xffffffffu, sum, o);
        alpha[tid] = ex / sum;
    }
    __syncthreads();

    float ctx = 0.f;
#pragma unroll 8
    for (int t = 0; t < TT; t++)
        ctx += alpha[t] * g_lstm_out[(b * TT + t) * DIN + tid];
    const float v = (ctx > 0.f) ? ctx : 0.5f * ctx;
    red[tid] = v * Wo[tid];
    __syncthreads();
#pragma unroll
    for (int s = 64; s > 0; s >>= 1) {
        if (tid < s) red[tid] += red[tid + s];
        __syncthreads();
    }
    if (tid == 0) out[b] = 1.f / (1.f + __expf(-(red[0] + bo[0])));
}

// =========================================================================
extern "C" void kernel_launch(void* const* d_in, const int* in_sizes, int n_in,
                              void* d_out, int out_size) {
    const float* x     = (const float*)d_in[0];
    // d_in[1] = visit_lens (int64) — unused by the reference math
    const float* emb   = (const float*)d_in[2];
    const float* Wg    = (const float*)d_in[3];
    const float* bg    = (const float*)d_in[4];
    const float* Wih_f = (const float*)d_in[5];
    const float* Whh_f = (const float*)d_in[6];
    const float* b_f   = (const float*)d_in[7];
    const float* Wih_b = (const float*)d_in[8];
    const float* Whh_b = (const float*)d_in[9];
    const float* b_b   = (const float*)d_in[10];
    const float* Wa    = (const float*)d_in[11];
    const float* ba    = (const float*)d_in[12];
    const float* ua    = (const float*)d_in[13];
    const float* Wo    = (const float*)d_in[14];
    const float* bo    = (const float*)d_in[15];
    float* out = (float*)d_out;

    k1_codes<<<dim3(TT, CSPLIT), 256>>>(x, emb);
    k2_prep<<<TT, 512>>>(Wg, bg, Wih_f, b_f, Wih_b, b_b);
    k3_lstm<<<16, 256>>>(Whh_f, Whh_b);
    k4_attn<<<BB * TT / 4, 256>>>(Wa, ba, ua);
    k5_head<<<BB, 128>>>(Wo, bo, out);
}

// round 9
// speedup vs baseline: 1.6481x; 1.0286x over previous
#include <cuda_runtime.h>
#include <cstdint>

// Problem constants
#define BB 8
#define TT 32
#define CC 4880
#define DD 64
#define HH 64
#define AA 256
#define NG 256        // 4*H gate width
#define DIN 128       // 2*D
#define CSPLIT 8

// ---------------- scratch (device globals; no allocation) ----------------
__device__ float g_Spart[CSPLIT][TT][BB][DD];   // partial code sums
__device__ float g_CntPart[CSPLIT][TT][BB];     // partial nonzero counts
__device__ float g_Z[2][BB][TT][NG];            // input projections (dir, b, t, gate)
__device__ float g_lstm_out[BB * TT * 2 * HH];  // [b][t][128]
__device__ float g_e[BB * TT];                  // attention logits

// ---------------- math helpers ----------------
__device__ __forceinline__ float sigf(float x) {
    return 1.0f / (1.0f + __expf(-x));
}
__device__ __forceinline__ float tanhf_fast(float x) {
    return 1.0f - 2.0f / (__expf(2.0f * x) + 1.0f);
}

// =========================================================================
// K1: partial sums S[b,t,d] = sum_c x[b,t,c] * emb[c,d]  + count partials
// grid (32 t, 8 split), 256 threads (8 warps).
// =========================================================================
__global__ void __launch_bounds__(256) k1_codes(const float* __restrict__ x,
                                                const float* __restrict__ emb) {
    const int t = blockIdx.x, split = blockIdx.y;
    const int w = threadIdx.x >> 5, lane = threadIdx.x & 31;
    const int d0 = lane * 2;

    float acc[BB][2];
    float csum[BB];
#pragma unroll
    for (int b = 0; b < BB; b++) { acc[b][0] = 0.f; acc[b][1] = 0.f; csum[b] = 0.f; }

#pragma unroll 2
    for (int gi = split; gi * 32 < CC; gi += CSPLIT) {
        const int c0 = gi * 32 + w * 4;
        if (c0 < CC) {
            float2 e2[4];
#pragma unroll
            for (int ccx = 0; ccx < 4; ccx++)
                e2[ccx] = *(const float2*)&emb[(c0 + ccx) * DD + d0];
#pragma unroll
            for (int b = 0; b < BB; b++) {
                const float4 xv = *(const float4*)&x[(size_t)(b * TT + t) * CC + c0];
                acc[b][0] += xv.x * e2[0].x + xv.y * e2[1].x + xv.z * e2[2].x + xv.w * e2[3].x;
                acc[b][1] += xv.x * e2[0].y + xv.y * e2[1].y + xv.z * e2[2].y + xv.w * e2[3].y;
                csum[b] += (xv.x + xv.y) + (xv.z + xv.w);
            }
        }
    }

    __shared__ float2 wp[8][BB][DD / 2];
    __shared__ float cw[8][BB];
#pragma unroll
    for (int b = 0; b < BB; b++)
        wp[w][b][lane] = make_float2(acc[b][0], acc[b][1]);
    if (lane == 0) {
#pragma unroll
        for (int b = 0; b < BB; b++) cw[w][b] = csum[b];
    }
    __syncthreads();

    for (int o = threadIdx.x; o < BB * DD; o += 256) {
        const int b = o >> 6, d = o & 63;
        float s = 0.f;
#pragma unroll
        for (int ww = 0; ww < 8; ww++) {
            const float2 v = wp[ww][b][d >> 1];
            s += (d & 1) ? v.y : v.x;
        }
        g_Spart[split][t][b][d] = s;
    }
    if (threadIdx.x < BB) {
        float s = 0.f;
#pragma unroll
        for (int ww = 0; ww < 8; ww++) s += cw[ww][threadIdx.x];
        g_CntPart[split][t][threadIdx.x] = s;
    }
}

// =========================================================================
// K2: per t: counts, avg_xt, avg_ht, z projection. grid 32, 512 threads.
// Wih chunks double-buffered through smem (register prefetch, 1 barrier
// per chunk) so staging latency overlaps compute.
// =========================================================================
__global__ void __launch_bounds__(512) k2_prep(const float* __restrict__ Wg,
                                               const float* __restrict__ bg,
                                               const float* __restrict__ Wih_f,
                                               const float* __restrict__ b_f,
                                               const float* __restrict__ Wih_b,
                                               const float* __restrict__ b_b) {
    const int t = blockIdx.x;
    const int tid = threadIdx.x;
    __shared__ float rows[BB][DIN];         // [b][0:64]=avg_ht, [64:128]=avg_xt
    __shared__ float4 wbuf2[2][2][512];     // 32KB: [dir][slot][8 k-rows x 64 quads]
    __shared__ float cnt_sm[BB], has_sm[BB];

    // ---- stage Wg into wbuf2 (first 1024 float4) ----
    {
        const float4* src = (const float4*)Wg;
        float4* dst = (float4*)wbuf2;
        dst[tid] = src[tid];
        dst[tid + 512] = src[tid + 512];
    }
    // ---- counts from partials ----
    if (tid < BB) {
        float s = 0.f;
#pragma unroll
        for (int sp = 0; sp < CSPLIT; sp++) s += g_CntPart[sp][t][tid];
        cnt_sm[tid] = fmaxf(s, 1.f);
        has_sm[tid] = (s > 0.f) ? 1.f : 0.f;
    }
    __syncthreads();

    // ---- avg_xt: 512 outputs, one per thread ----
    {
        const int b = tid >> 6, d = tid & 63;
        float s = 0.f;
#pragma unroll
        for (int sp = 0; sp < CSPLIT; sp++) s += g_Spart[sp][t][b][d];
        rows[b][DD + d] = s / cnt_sm[b];
    }
    __syncthreads();

    // ---- avg_ht = avg_xt @ Wg + bg*has (Wg from smem) ----
    {
        const int b = tid >> 6, d = tid & 63;
        const float* wg_sm = (const float*)wbuf2;
        float a = bg[d] * has_sm[b];
#pragma unroll 16
        for (int k = 0; k < DD; k++) a += rows[b][DD + k] * wg_sm[k * DD + d];
        rows[b][d] = a;
    }
    __syncthreads();

    // ---- z = lstm_in @ Wih + bias : half block per dir, double-buffered ----
    const int dir = tid >> 8;
    const int tid2 = tid & 255;
    const float* __restrict__ Wih  = dir ? Wih_b : Wih_f;
    const float* __restrict__ bias = dir ? b_b : b_f;
    const int q = tid2 & 63, bg2 = tid2 >> 6;   // gate quad, b-pair index
    const int b0 = bg2 * 2;
    const float4 bv = *(const float4*)&bias[q * 4];
    float acc0[4] = {bv.x, bv.y, bv.z, bv.w};
    float acc1[4] = {bv.x, bv.y, bv.z, bv.w};

    // preload chunk 0 (8 k-rows = 512 float4 per dir; 2 per thread)
    float4 ra = ((const float4*)Wih)[tid2];
    float4 rb = ((const float4*)Wih)[tid2 + 256];
    {
        float4* ds = &wbuf2[dir][0][0];
        ds[tid2] = ra;
        ds[tid2 + 256] = rb;
    }
    __syncthreads();

    for (int ch = 0; ch < 16; ch++) {
        const int slot = ch & 1;
        // prefetch next chunk into registers (overlaps with compute below)
        if (ch < 15) {
            const float4* wsrc = (const float4*)&Wih[(ch + 1) * 8 * NG];
            ra = wsrc[tid2];
            rb = wsrc[tid2 + 256];
        }
        const float4* cs = &wbuf2[dir][slot][0];
#pragma unroll
        for (int kk = 0; kk < 8; kk++) {
            const float4 wv = cs[kk * 64 + q];
            const int k = ch * 8 + kk;
            const float r0 = rows[b0][k];
            const float r1 = rows[b0 + 1][k];
            acc0[0] += r0 * wv.x; acc0[1] += r0 * wv.y; acc0[2] += r0 * wv.z; acc0[3] += r0 * wv.w;
            acc1[0] += r1 * wv.x; acc1[1] += r1 * wv.y; acc1[2] += r1 * wv.z; acc1[3] += r1 * wv.w;
        }
        if (ch < 15) {
            float4* ds = &wbuf2[dir][slot ^ 1][0];
            ds[tid2] = ra;
            ds[tid2 + 256] = rb;
        }
        __syncthreads();
    }
    *(float4*)&g_Z[dir][b0][t][q * 4]     = make_float4(acc0[0], acc0[1], acc0[2], acc0[3]);
    *(float4*)&g_Z[dir][b0 + 1][t][q * 4] = make_float4(acc1[0], acc1[1], acc1[2], acc1[3]);
}

// =========================================================================
// K3: bidirectional LSTM, split by (dir, batch). grid=16, 256 threads.
// Thread g owns gate column g of Whh (register-resident, k-paired f32x2,
// 4 independent accumulators to break the RAW chain); h via smem;
// z input prefetched one step ahead.
// =========================================================================
__global__ void __launch_bounds__(256, 1) k3_lstm(const float* __restrict__ Whh_f,
                                                  const float* __restrict__ Whh_b) {
    const int dir = blockIdx.x >> 3;
    const int b = blockIdx.x & 7;
    const float* __restrict__ Whh = dir ? Whh_b : Whh_f;
    __shared__ float h_sm[HH];
    __shared__ float z_sm[NG];
    const int g = threadIdx.x;

    unsigned long long wpk[32];
#pragma unroll
    for (int i = 0; i < 32; i++) {
        const float w0 = Whh[(2 * i) * NG + g];
        const float w1 = Whh[(2 * i + 1) * NG + g];
        asm("mov.b64 %0, {%1, %2};" : "=l"(wpk[i]) : "f"(w0), "f"(w1));
    }
    if (g < HH) h_sm[g] = 0.f;
    float cst = 0.f;
    __syncthreads();

    const float* __restrict__ zrow = &g_Z[dir][b][0][0];
    float* __restrict__ orow = &g_lstm_out[b * TT * (2 * HH) + dir * HH];

    const int t0 = dir ? (TT - 1) : 0;
    float zcur = zrow[t0 * NG + g];

    for (int s = 0; s < TT; s++) {
        const int t = dir ? (TT - 1 - s) : s;
        float znext = 0.f;
        if (s + 1 < TT) {
            const int tn = dir ? (TT - 2 - s) : (s + 1);
            znext = zrow[tn * NG + g];
        }
        // 4 independent f32x2 accumulators: RAW chain 128 -> ~32 cyc
        unsigned long long a0 = 0ull, a1 = 0ull, a2 = 0ull, a3 = 0ull;
        const ulonglong2* hp = (const ulonglong2*)h_sm;
#pragma unroll
        for (int i = 0; i < 16; i += 2) {
            const ulonglong2 h0 = hp[i];
            const ulonglong2 h1 = hp[i + 1];
            asm("fma.rn.f32x2 %0, %1, %2, %0;" : "+l"(a0) : "l"(wpk[2 * i]),     "l"(h0.x));
            asm("fma.rn.f32x2 %0, %1, %2, %0;" : "+l"(a1) : "l"(wpk[2 * i + 1]), "l"(h0.y));
            asm("fma.rn.f32x2 %0, %1, %2, %0;" : "+l"(a2) : "l"(wpk[2 * i + 2]), "l"(h1.x));
            asm("fma.rn.f32x2 %0, %1, %2, %0;" : "+l"(a3) : "l"(wpk[2 * i + 3]), "l"(h1.y));
        }
        float l0, h0f, l1, h1f, l2, h2f, l3, h3f;
        asm("mov.b64 {%0, %1}, %2;" : "=f"(l0), "=f"(h0f) : "l"(a0));
        asm("mov.b64 {%0, %1}, %2;" : "=f"(l1), "=f"(h1f) : "l"(a1));
        asm("mov.b64 {%0, %1}, %2;" : "=f"(l2), "=f"(h2f) : "l"(a2));
        asm("mov.b64 {%0, %1}, %2;" : "=f"(l3), "=f"(h3f) : "l"(a3));
        z_sm[g] = zcur + ((l0 + h0f) + (l1 + h1f)) + ((l2 + h2f) + (l3 + h3f));
        __syncthreads();

        if (g < HH) {
            const float ziv = z_sm[g];
            const float zfv = z_sm[64 + g];
            const float zgv = z_sm[128 + g];
            const float zov = z_sm[192 + g];
            const float ig = sigf(ziv), fg = sigf(zfv);
            const float gg = tanhf_fast(zgv), og = sigf(zov);
            cst = fg * cst + ig * gg;
            const float hnew = og * tanhf_fast(cst);
            h_sm[g] = hnew;
            orow[t * (2 * HH) + g] = hnew;
        }
        __syncthreads();
        zcur = znext;
    }
}

// =========================================================================
// K4: attention logits e[b,t] = tanh(row @ Wa + ba) . ua
// grid 64 (4 rows each), 256 threads. Wa double-buffered through smem:
// register prefetch of chunk ch+1 overlaps compute of chunk ch; one
// barrier per chunk.
// =========================================================================
__global__ void __launch_bounds__(256) k4_attn(const float* __restrict__ Wa,
                                               const float* __restrict__ ba,
                                               const float* __restrict__ ua) {
    const int bt0 = blockIdx.x * 4;
    const int tid = threadIdx.x;
    const int q = tid & 63;       // col quad (cols q*4..q*4+3)
    const int rg = tid >> 6;      // row 0..3
    __shared__ float rows[4][DIN];         // 2KB
    __shared__ float4 wbuf[2][16][DD];     // 32KB: 2 slots of 16 k-rows x 64 quads
    __shared__ float red[8];               // per-warp partials

    // stage 4 rows (512 floats = 128 float4)
    if (tid < 128) {
        ((float4*)rows)[tid] = ((const float4*)&g_lstm_out[bt0 * DIN])[tid];
    }
    const float4 bav = *(const float4*)&ba[q * 4];
    float acc0 = bav.x, acc1 = bav.y, acc2 = bav.z, acc3 = bav.w;

    // preload chunk 0 (16 k-rows = 1024 float4; 4 per thread)
    float4 w0 = ((const float4*)Wa)[tid];
    float4 w1 = ((const float4*)Wa)[tid + 256];
    float4 w2 = ((const float4*)Wa)[tid + 512];
    float4 w3 = ((const float4*)Wa)[tid + 768];
    {
        float4* ds = (float4*)wbuf[0];
        ds[tid] = w0; ds[tid + 256] = w1; ds[tid + 512] = w2; ds[tid + 768] = w3;
    }
    __syncthreads();

    for (int ch = 0; ch < 8; ch++) {
        const int slot = ch & 1;
        if (ch < 7) {
            const float4* wsrc = (const float4*)&Wa[(ch + 1) * 16 * AA];
            w0 = wsrc[tid]; w1 = wsrc[tid + 256]; w2 = wsrc[tid + 512]; w3 = wsrc[tid + 768];
        }
#pragma unroll
        for (int kk = 0; kk < 16; kk++) {
            const float4 wv = wbuf[slot][kk][q];
            const float v = rows[rg][ch * 16 + kk];
            acc0 += v * wv.x; acc1 += v * wv.y; acc2 += v * wv.z; acc3 += v * wv.w;
        }
        if (ch < 7) {
            float4* ds = (float4*)wbuf[slot ^ 1];
            ds[tid] = w0; ds[tid + 256] = w1; ds[tid + 512] = w2; ds[tid + 768] = w3;
        }
        __syncthreads();
    }

    const float4 uav = *(const float4*)&ua[q * 4];
    float p = tanhf_fast(acc0) * uav.x + tanhf_fast(acc1) * uav.y
            + tanhf_fast(acc2) * uav.z + tanhf_fast(acc3) * uav.w;
#pragma unroll
    for (int o = 16; o > 0; o >>= 1) p += __shfl_down_sync(0xffffffffu, p, o);
    const int wid = tid >> 5;   // warps (2*rg, 2*rg+1) cover row rg
    if ((tid & 31) == 0) red[wid] = p;
    __syncthreads();
    if (tid < 4) g_e[bt0 + tid] = red[tid * 2] + red[tid * 2 + 1];
}

// =========================================================================
// K5: softmax over t, context, leaky_relu, output head. grid 8 (b), 128 thr.
// =========================================================================
__global__ void __launch_bounds__(128) k5_head(const float* __restrict__ Wo,
                                               const float* __restrict__ bo,
                                               float* __restrict__ out) {
    const int b = blockIdx.x;
    const int tid = threadIdx.x;
    __shared__ float alpha[TT];
    __shared__ float red[128];

    if (tid < 32) {
        float e = g_e[b * TT + tid];
        float m = e;
#pragma unroll
        for (int o = 16; o > 0; o >>= 1) m = fmaxf(m, __shfl_xor_sync(0xffffffffu, m, o));
        float ex = __expf(e - m);
        float sum = ex;
#pragma unroll
        for (int o = 16; o > 0; o >>= 1) sum += __shfl_xor_sync(0xffffffffu, sum, o);
        alpha[tid] = ex / sum;
    }
    __syncthreads();

    float ctx = 0.f;
#pragma unroll 8
    for (int t = 0; t < TT; t++)
        ctx += alpha[t] * g_lstm_out[(b * TT + t) * DIN + tid];
    const float v = (ctx > 0.f) ? ctx : 0.5f * ctx;
    red[tid] = v * Wo[tid];
    __syncthreads();
#pragma unroll
    for (int s = 64; s > 0; s >>= 1) {
        if (tid < s) red[tid] += red[tid + s];
        __syncthreads();
    }
    if (tid == 0) out[b] = 1.f / (1.f + __expf(-(red[0] + bo[0])));
}

// =========================================================================
extern "C" void kernel_launch(void* const* d_in, const int* in_sizes, int n_in,
                              void* d_out, int out_size) {
    const float* x     = (const float*)d_in[0];
    // d_in[1] = visit_lens (int64) — unused by the reference math
    const float* emb   = (const float*)d_in[2];
    const float* Wg    = (const float*)d_in[3];
    const float* bg    = (const float*)d_in[4];
    const float* Wih_f = (const float*)d_in[5];
    const float* Whh_f = (const float*)d_in[6];
    const float* b_f   = (const float*)d_in[7];
    const float* Wih_b = (const float*)d_in[8];
    const float* Whh_b = (const float*)d_in[9];
    const float* b_b   = (const float*)d_in[10];
    const float* Wa    = (const float*)d_in[11];
    const float* ba    = (const float*)d_in[12];
    const float* ua    = (const float*)d_in[13];
    const float* Wo    = (const float*)d_in[14];
    const float* bo    = (const float*)d_in[15];
    float* out = (float*)d_out;

    k1_codes<<<dim3(TT, CSPLIT), 256>>>(x, emb);
    k2_prep<<<TT, 512>>>(Wg, bg, Wih_f, b_f, Wih_b, b_b);
    k3_lstm<<<16, 256>>>(Whh_f, Whh_b);
    k4_attn<<<BB * TT / 4, 256>>>(Wa, ba, ua);
    k5_head<<<BB, 128>>>(Wo, bo, out);
}

// round 10
// speedup vs baseline: 1.7018x; 1.0326x over previous
#include <cuda_runtime.h>
#include <cstdint>

// Problem constants
#define BB 8
#define TT 32
#define CC 4880
#define DD 64
#define HH 64
#define AA 256
#define NG 256        // 4*H gate width
#define DIN 128       // 2*D
#define CSPLIT 8

// ---------------- scratch (device globals; no allocation) ----------------
__device__ float g_Spart[CSPLIT][TT][BB][DD];   // partial code sums
__device__ float g_CntPart[CSPLIT][TT][BB];     // partial nonzero counts
__device__ float g_Z[2][BB][TT][NG];            // input projections (dir, b, t, gate)
__device__ float g_lstm_out[BB * TT * 2 * HH];  // [b][t][128]
__device__ float g_epart[8][BB * TT];           // attention logit partials (col-group)

// ---------------- math helpers ----------------
__device__ __forceinline__ float sigf(float x) {
    return 1.0f / (1.0f + __expf(-x));
}
__device__ __forceinline__ float tanhf_fast(float x) {
    return 1.0f - 2.0f / (__expf(2.0f * x) + 1.0f);
}

// =========================================================================
// K1: partial sums S[b,t,d] = sum_c x[b,t,c] * emb[c,d]  + count partials
// grid (32 t, 8 split), 256 threads (8 warps).
// =========================================================================
__global__ void __launch_bounds__(256) k1_codes(const float* __restrict__ x,
                                                const float* __restrict__ emb) {
    const int t = blockIdx.x, split = blockIdx.y;
    const int w = threadIdx.x >> 5, lane = threadIdx.x & 31;
    const int d0 = lane * 2;

    float acc[BB][2];
    float csum[BB];
#pragma unroll
    for (int b = 0; b < BB; b++) { acc[b][0] = 0.f; acc[b][1] = 0.f; csum[b] = 0.f; }

#pragma unroll 2
    for (int gi = split; gi * 32 < CC; gi += CSPLIT) {
        const int c0 = gi * 32 + w * 4;
        if (c0 < CC) {
            float2 e2[4];
#pragma unroll
            for (int ccx = 0; ccx < 4; ccx++)
                e2[ccx] = *(const float2*)&emb[(c0 + ccx) * DD + d0];
#pragma unroll
            for (int b = 0; b < BB; b++) {
                const float4 xv = *(const float4*)&x[(size_t)(b * TT + t) * CC + c0];
                acc[b][0] += xv.x * e2[0].x + xv.y * e2[1].x + xv.z * e2[2].x + xv.w * e2[3].x;
                acc[b][1] += xv.x * e2[0].y + xv.y * e2[1].y + xv.z * e2[2].y + xv.w * e2[3].y;
                csum[b] += (xv.x + xv.y) + (xv.z + xv.w);
            }
        }
    }

    __shared__ float2 wp[8][BB][DD / 2];
    __shared__ float cw[8][BB];
#pragma unroll
    for (int b = 0; b < BB; b++)
        wp[w][b][lane] = make_float2(acc[b][0], acc[b][1]);
    if (lane == 0) {
#pragma unroll
        for (int b = 0; b < BB; b++) cw[w][b] = csum[b];
    }
    __syncthreads();

    for (int o = threadIdx.x; o < BB * DD; o += 256) {
        const int b = o >> 6, d = o & 63;
        float s = 0.f;
#pragma unroll
        for (int ww = 0; ww < 8; ww++) {
            const float2 v = wp[ww][b][d >> 1];
            s += (d & 1) ? v.y : v.x;
        }
        g_Spart[split][t][b][d] = s;
    }
    if (threadIdx.x < BB) {
        float s = 0.f;
#pragma unroll
        for (int ww = 0; ww < 8; ww++) s += cw[ww][threadIdx.x];
        g_CntPart[split][t][threadIdx.x] = s;
    }
}

// =========================================================================
// K2: per t: counts, avg_xt, avg_ht, z projection. grid 32, 512 threads.
// Wih chunks double-buffered through smem (register prefetch, 1 barrier
// per chunk) so staging latency overlaps compute.
// =========================================================================
__global__ void __launch_bounds__(512) k2_prep(const float* __restrict__ Wg,
                                               const float* __restrict__ bg,
                                               const float* __restrict__ Wih_f,
                                               const float* __restrict__ b_f,
                                               const float* __restrict__ Wih_b,
                                               const float* __restrict__ b_b) {
    const int t = blockIdx.x;
    const int tid = threadIdx.x;
    __shared__ float rows[BB][DIN];         // [b][0:64]=avg_ht, [64:128]=avg_xt
    __shared__ float4 wbuf2[2][2][512];     // 32KB: [dir][slot][8 k-rows x 64 quads]
    __shared__ float cnt_sm[BB], has_sm[BB];

    // ---- stage Wg into wbuf2 (first 1024 float4) ----
    {
        const float4* src = (const float4*)Wg;
        float4* dst = (float4*)wbuf2;
        dst[tid] = src[tid];
        dst[tid + 512] = src[tid + 512];
    }
    // ---- counts from partials ----
    if (tid < BB) {
        float s = 0.f;
#pragma unroll
        for (int sp = 0; sp < CSPLIT; sp++) s += g_CntPart[sp][t][tid];
        cnt_sm[tid] = fmaxf(s, 1.f);
        has_sm[tid] = (s > 0.f) ? 1.f : 0.f;
    }
    __syncthreads();

    // ---- avg_xt: 512 outputs, one per thread ----
    {
        const int b = tid >> 6, d = tid & 63;
        float s = 0.f;
#pragma unroll
        for (int sp = 0; sp < CSPLIT; sp++) s += g_Spart[sp][t][b][d];
        rows[b][DD + d] = s / cnt_sm[b];
    }
    __syncthreads();

    // ---- avg_ht = avg_xt @ Wg + bg*has (Wg from smem) ----
    {
        const int b = tid >> 6, d = tid & 63;
        const float* wg_sm = (const float*)wbuf2;
        float a = bg[d] * has_sm[b];
#pragma unroll 16
        for (int k = 0; k < DD; k++) a += rows[b][DD + k] * wg_sm[k * DD + d];
        rows[b][d] = a;
    }
    __syncthreads();

    // ---- z = lstm_in @ Wih + bias : half block per dir, double-buffered ----
    const int dir = tid >> 8;
    const int tid2 = tid & 255;
    const float* __restrict__ Wih  = dir ? Wih_b : Wih_f;
    const float* __restrict__ bias = dir ? b_b : b_f;
    const int q = tid2 & 63, bg2 = tid2 >> 6;   // gate quad, b-pair index
    const int b0 = bg2 * 2;
    const float4 bv = *(const float4*)&bias[q * 4];
    float acc0[4] = {bv.x, bv.y, bv.z, bv.w};
    float acc1[4] = {bv.x, bv.y, bv.z, bv.w};

    // preload chunk 0 (8 k-rows = 512 float4 per dir; 2 per thread)
    float4 ra = ((const float4*)Wih)[tid2];
    float4 rb = ((const float4*)Wih)[tid2 + 256];
    {
        float4* ds = &wbuf2[dir][0][0];
        ds[tid2] = ra;
        ds[tid2 + 256] = rb;
    }
    __syncthreads();

    for (int ch = 0; ch < 16; ch++) {
        const int slot = ch & 1;
        // prefetch next chunk into registers (overlaps with compute below)
        if (ch < 15) {
            const float4* wsrc = (const float4*)&Wih[(ch + 1) * 8 * NG];
            ra = wsrc[tid2];
            rb = wsrc[tid2 + 256];
        }
        const float4* cs = &wbuf2[dir][slot][0];
#pragma unroll
        for (int kk = 0; kk < 8; kk++) {
            const float4 wv = cs[kk * 64 + q];
            const int k = ch * 8 + kk;
            const float r0 = rows[b0][k];
            const float r1 = rows[b0 + 1][k];
            acc0[0] += r0 * wv.x; acc0[1] += r0 * wv.y; acc0[2] += r0 * wv.z; acc0[3] += r0 * wv.w;
            acc1[0] += r1 * wv.x; acc1[1] += r1 * wv.y; acc1[2] += r1 * wv.z; acc1[3] += r1 * wv.w;
        }
        if (ch < 15) {
            float4* ds = &wbuf2[dir][slot ^ 1][0];
            ds[tid2] = ra;
            ds[tid2 + 256] = rb;
        }
        __syncthreads();
    }
    *(float4*)&g_Z[dir][b0][t][q * 4]     = make_float4(acc0[0], acc0[1], acc0[2], acc0[3]);
    *(float4*)&g_Z[dir][b0 + 1][t][q * 4] = make_float4(acc1[0], acc1[1], acc1[2], acc1[3]);
}

// =========================================================================
// K3: bidirectional LSTM, split by (dir, batch). grid=16, 256 threads.
// Thread g owns gate column g of Whh (register-resident, k-paired f32x2,
// 4 independent accumulators to break the RAW chain); h via smem;
// z input prefetched one step ahead.
// =========================================================================
__global__ void __launch_bounds__(256, 1) k3_lstm(const float* __restrict__ Whh_f,
                                                  const float* __restrict__ Whh_b) {
    const int dir = blockIdx.x >> 3;
    const int b = blockIdx.x & 7;
    const float* __restrict__ Whh = dir ? Whh_b : Whh_f;
    __shared__ float h_sm[HH];
    __shared__ float z_sm[NG];
    const int g = threadIdx.x;

    unsigned long long wpk[32];
#pragma unroll
    for (int i = 0; i < 32; i++) {
        const float w0 = Whh[(2 * i) * NG + g];
        const float w1 = Whh[(2 * i + 1) * NG + g];
        asm("mov.b64 %0, {%1, %2};" : "=l"(wpk[i]) : "f"(w0), "f"(w1));
    }
    if (g < HH) h_sm[g] = 0.f;
    float cst = 0.f;
    __syncthreads();

    const float* __restrict__ zrow = &g_Z[dir][b][0][0];
    float* __restrict__ orow = &g_lstm_out[b * TT * (2 * HH) + dir * HH];

    const int t0 = dir ? (TT - 1) : 0;
    float zcur = zrow[t0 * NG + g];

    for (int s = 0; s < TT; s++) {
        const int t = dir ? (TT - 1 - s) : s;
        float znext = 0.f;
        if (s + 1 < TT) {
            const int tn = dir ? (TT - 2 - s) : (s + 1);
            znext = zrow[tn * NG + g];
        }
        // 4 independent f32x2 accumulators: RAW chain 128 -> ~32 cyc
        unsigned long long a0 = 0ull, a1 = 0ull, a2 = 0ull, a3 = 0ull;
        const ulonglong2* hp = (const ulonglong2*)h_sm;
#pragma unroll
        for (int i = 0; i < 16; i += 2) {
            const ulonglong2 h0 = hp[i];
            const ulonglong2 h1 = hp[i + 1];
            asm("fma.rn.f32x2 %0, %1, %2, %0;" : "+l"(a0) : "l"(wpk[2 * i]),     "l"(h0.x));
            asm("fma.rn.f32x2 %0, %1, %2, %0;" : "+l"(a1) : "l"(wpk[2 * i + 1]), "l"(h0.y));
            asm("fma.rn.f32x2 %0, %1, %2, %0;" : "+l"(a2) : "l"(wpk[2 * i + 2]), "l"(h1.x));
            asm("fma.rn.f32x2 %0, %1, %2, %0;" : "+l"(a3) : "l"(wpk[2 * i + 3]), "l"(h1.y));
        }
        float l0, h0f, l1, h1f, l2, h2f, l3, h3f;
        asm("mov.b64 {%0, %1}, %2;" : "=f"(l0), "=f"(h0f) : "l"(a0));
        asm("mov.b64 {%0, %1}, %2;" : "=f"(l1), "=f"(h1f) : "l"(a1));
        asm("mov.b64 {%0, %1}, %2;" : "=f"(l2), "=f"(h2f) : "l"(a2));
        asm("mov.b64 {%0, %1}, %2;" : "=f"(l3), "=f"(h3f) : "l"(a3));
        z_sm[g] = zcur + ((l0 + h0f) + (l1 + h1f)) + ((l2 + h2f) + (l3 + h3f));
        __syncthreads();

        if (g < HH) {
            const float ziv = z_sm[g];
            const float zfv = z_sm[64 + g];
            const float zgv = z_sm[128 + g];
            const float zov = z_sm[192 + g];
            const float ig = sigf(ziv), fg = sigf(zfv);
            const float gg = tanhf_fast(zgv), og = sigf(zov);
            cst = fg * cst + ig * gg;
            const float hnew = og * tanhf_fast(cst);
            h_sm[g] = hnew;
            orow[t * (2 * HH) + g] = hnew;
        }
        __syncthreads();
        zcur = znext;
    }
}

// =========================================================================
// K4: attention logit partials, column-split.
// grid 64 = (8 col-groups cg) x (8 row-groups rg). Block stages its
// Wa[:, cg*32:+32] slice (16KB, ONCE) + 32 lstm_out rows, computes
// acc[bt, col] fully, tanh, *ua, reduces over its 32 cols ->
// g_epart[cg][bt]. No chunk loop, one barrier.
// =========================================================================
__global__ void __launch_bounds__(256) k4_attn(const float* __restrict__ Wa,
                                               const float* __restrict__ ba,
                                               const float* __restrict__ ua) {
    const int cg = blockIdx.x & 7;        // col group: cols cg*32..+31
    const int rg = blockIdx.x >> 3;       // row group: bt rows rg*32..+31
    const int tid = threadIdx.x;
    const int lane = tid & 31, w = tid >> 5;
    const int col = cg * 32 + lane;
    __shared__ float rows_sm[32][DIN];    // 16KB
    __shared__ float wa_sm[DIN][32];      // 16KB  [k][c]

    // stage 32 lstm_out rows: 1024 float4 / 256 threads
    {
        const float4* src = (const float4*)&g_lstm_out[rg * 32 * DIN];
        float4* dst = (float4*)rows_sm;
#pragma unroll
        for (int i = 0; i < 4; i++) dst[tid + i * 256] = src[tid + i * 256];
    }
    // stage Wa column slice [128][32]: 1024 float4 / 256 threads
    {
#pragma unroll
        for (int i = 0; i < 4; i++) {
            const int idx = tid + i * 256;      // float4 index
            const int k = idx >> 3, seg = idx & 7;
            *(float4*)&wa_sm[k][seg * 4] =
                *(const float4*)&Wa[k * AA + cg * 32 + seg * 4];
        }
    }
    __syncthreads();

    // warp w -> local rows w*4..w*4+3; lane -> col
    float acc0 = 0.f, acc1 = 0.f, acc2 = 0.f, acc3 = 0.f;
    const int r0 = w * 4;
#pragma unroll 4
    for (int kq = 0; kq < 32; kq++) {
        const float4 a0 = *(const float4*)&rows_sm[r0 + 0][kq * 4];
        const float4 a1 = *(const float4*)&rows_sm[r0 + 1][kq * 4];
        const float4 a2 = *(const float4*)&rows_sm[r0 + 2][kq * 4];
        const float4 a3 = *(const float4*)&rows_sm[r0 + 3][kq * 4];
        const float w0 = wa_sm[kq * 4 + 0][lane];
        const float w1 = wa_sm[kq * 4 + 1][lane];
        const float w2 = wa_sm[kq * 4 + 2][lane];
        const float w3 = wa_sm[kq * 4 + 3][lane];
        acc0 += a0.x * w0 + a0.y * w1 + a0.z * w2 + a0.w * w3;
        acc1 += a1.x * w0 + a1.y * w1 + a1.z * w2 + a1.w * w3;
        acc2 += a2.x * w0 + a2.y * w1 + a2.z * w2 + a2.w * w3;
        acc3 += a3.x * w0 + a3.y * w1 + a3.z * w2 + a3.w * w3;
    }
    const float bav = ba[col], uav = ua[col];
    float p0 = tanhf_fast(acc0 + bav) * uav;
    float p1 = tanhf_fast(acc1 + bav) * uav;
    float p2 = tanhf_fast(acc2 + bav) * uav;
    float p3 = tanhf_fast(acc3 + bav) * uav;
#pragma unroll
    for (int o = 16; o > 0; o >>= 1) {
        p0 += __shfl_down_sync(0xffffffffu, p0, o);
        p1 += __shfl_down_sync(0xffffffffu, p1, o);
        p2 += __shfl_down_sync(0xffffffffu, p2, o);
        p3 += __shfl_down_sync(0xffffffffu, p3, o);
    }
    if (lane == 0) {
        const int bt = rg * 32 + r0;
        g_epart[cg][bt + 0] = p0;
        g_epart[cg][bt + 1] = p1;
        g_epart[cg][bt + 2] = p2;
        g_epart[cg][bt + 3] = p3;
    }
}

// =========================================================================
// K5: sum logit partials, softmax over t, context, leaky_relu, head.
// grid 8 (b), 128 threads.
// =========================================================================
__global__ void __launch_bounds__(128) k5_head(const float* __restrict__ Wo,
                                               const float* __restrict__ bo,
                                               float* __restrict__ out) {
    const int b = blockIdx.x;
    const int tid = threadIdx.x;
    __shared__ float alpha[TT];
    __shared__ float red[128];

    if (tid < 32) {
        float e = 0.f;
#pragma unroll
        for (int cg = 0; cg < 8; cg++) e += g_epart[cg][b * TT + tid];
        float m = e;
#pragma unroll
        for (int o = 16; o > 0; o >>= 1) m = fmaxf(m, __shfl_xor_sync(0xffffffffu, m, o));
        float ex = __expf(e - m);
        float sum = ex;
#pragma unroll
        for (int o = 16; o > 0; o >>= 1) sum += __shfl_xor_sync(0xffffffffu, sum, o);
        alpha[tid] = ex / sum;
    }
    __syncthreads();

    float ctx = 0.f;
#pragma unroll 8
    for (int t = 0; t < TT; t++)
        ctx += alpha[t] * g_lstm_out[(b * TT + t) * DIN + tid];
    const float v = (ctx > 0.f) ? ctx : 0.5f * ctx;
    red[tid] = v * Wo[tid];
    __syncthreads();
#pragma unroll
    for (int s = 64; s > 0; s >>= 1) {
        if (tid < s) red[tid] += red[tid + s];
        __syncthreads();
    }
    if (tid == 0) out[b] = 1.f / (1.f + __expf(-(red[0] + bo[0])));
}

// =========================================================================
extern "C" void kernel_launch(void* const* d_in, const int* in_sizes, int n_in,
                              void* d_out, int out_size) {
    const float* x     = (const float*)d_in[0];
    // d_in[1] = visit_lens (int64) — unused by the reference math
    const float* emb   = (const float*)d_in[2];
    const float* Wg    = (const float*)d_in[3];
    const float* bg    = (const float*)d_in[4];
    const float* Wih_f = (const float*)d_in[5];
    const float* Whh_f = (const float*)d_in[6];
    const float* b_f   = (const float*)d_in[7];
    const float* Wih_b = (const float*)d_in[8];
    const float* Whh_b = (const float*)d_in[9];
    const float* b_b   = (const float*)d_in[10];
    const float* Wa    = (const float*)d_in[11];
    const float* ba    = (const float*)d_in[12];
    const float* ua    = (const float*)d_in[13];
    const float* Wo    = (const float*)d_in[14];
    const float* bo    = (const float*)d_in[15];
    float* out = (float*)d_out;

    k1_codes<<<dim3(TT, CSPLIT), 256>>>(x, emb);
    k2_prep<<<TT, 512>>>(Wg, bg, Wih_f, b_f, Wih_b, b_b);
    k3_lstm<<<16, 256>>>(Whh_f, Whh_b);
    k4_attn<<<64, 256>>>(Wa, ba, ua);
    k5_head<<<BB, 128>>>(Wo, bo, out);
}